// round 1
// baseline (speedup 1.0000x reference)
#include <cuda_runtime.h>

#define D_MODEL 1024
#define NHEADS  16
#define DHEAD   64
#define BATCH   4
#define SEQ     2048
#define MTOT    (BATCH*SEQ)   // 8192

// Scratch (static device globals — allocation-free per harness rules). 134 MB.
__device__ float g_q[MTOT*D_MODEL];
__device__ float g_k[MTOT*D_MODEL];
__device__ float g_v[MTOT*D_MODEL];
__device__ float g_ctx[MTOT*D_MODEL];

// ---------------------------------------------------------------------------
// C[M,N] = A[M,K] @ B[N,K]^T   (nn.Linear: y = x @ W.T, W stored row-major NxK)
// 128x128 block, BK=8, 8x8 per-thread microtile, 256 threads.
// ---------------------------------------------------------------------------
__device__ __forceinline__ void sgemm_nt_body(
    const float* __restrict__ A, const float* __restrict__ B,
    float* __restrict__ C, int M, int N, int K)
{
    const int BM = 128, BN = 128, BK = 8, TM = 8, TN = 8;
    __shared__ float As[BK][BM];
    __shared__ float Bs[BK][BN];

    int tid  = threadIdx.x;          // 0..255
    int row0 = blockIdx.y * BM;
    int col0 = blockIdx.x * BN;
    int lr   = tid >> 1;             // 0..127 : loaded row
    int lk   = (tid & 1) * 4;        // 0 or 4 : k offset
    int tx   = tid & 15;             // 0..15
    int ty   = tid >> 4;             // 0..15

    float acc[TM][TN];
#pragma unroll
    for (int i = 0; i < TM; ++i)
#pragma unroll
        for (int j = 0; j < TN; ++j) acc[i][j] = 0.0f;

    const float* Ap = A + (size_t)(row0 + lr) * K + lk;
    const float* Bp = B + (size_t)(col0 + lr) * K + lk;

    for (int k0 = 0; k0 < K; k0 += BK) {
        float4 a4 = *(const float4*)(Ap + k0);
        float4 b4 = *(const float4*)(Bp + k0);
        As[lk+0][lr] = a4.x; As[lk+1][lr] = a4.y;
        As[lk+2][lr] = a4.z; As[lk+3][lr] = a4.w;
        Bs[lk+0][lr] = b4.x; Bs[lk+1][lr] = b4.y;
        Bs[lk+2][lr] = b4.z; Bs[lk+3][lr] = b4.w;
        __syncthreads();

#pragma unroll
        for (int k = 0; k < BK; ++k) {
            float a[TM], b[TN];
#pragma unroll
            for (int i = 0; i < TM; i += 4)
                *(float4*)&a[i] = *(const float4*)&As[k][ty*TM + i];
#pragma unroll
            for (int j = 0; j < TN; j += 4)
                *(float4*)&b[j] = *(const float4*)&Bs[k][tx*TN + j];
#pragma unroll
            for (int i = 0; i < TM; ++i)
#pragma unroll
                for (int j = 0; j < TN; ++j)
                    acc[i][j] += a[i] * b[j];
        }
        __syncthreads();
    }

#pragma unroll
    for (int i = 0; i < TM; ++i) {
        float* Cp = C + (size_t)(row0 + ty*TM + i) * N + col0 + tx*TN;
#pragma unroll
        for (int j = 0; j < TN; j += 4) {
            float4 r = make_float4(acc[i][j], acc[i][j+1], acc[i][j+2], acc[i][j+3]);
            *(float4*)(Cp + j) = r;
        }
    }
}

__global__ void __launch_bounds__(256)
qkv_kernel(const float* __restrict__ x,
           const float* __restrict__ Wq,
           const float* __restrict__ Wk,
           const float* __restrict__ Wv)
{
    const float* W;
    float* out;
    if (blockIdx.z == 0)      { W = Wq; out = g_q; }
    else if (blockIdx.z == 1) { W = Wk; out = g_k; }
    else                      { W = Wv; out = g_v; }
    sgemm_nt_body(x, W, out, MTOT, D_MODEL, D_MODEL);
}

__global__ void __launch_bounds__(256)
oproj_kernel(const float* __restrict__ Wo, float* __restrict__ out)
{
    sgemm_nt_body(g_ctx, Wo, out, MTOT, D_MODEL, D_MODEL);
}

// ---------------------------------------------------------------------------
// Flash-attention style: one CTA = one (batch, head, 64-query tile).
// Streams 64-key K/V tiles, online softmax, fp32.
// Thread layout: 16x16; thread (ty,tx) owns rows 4ty..4ty+3, cols/keys 4tx..4tx+3.
// smem: QT[c][row], KT[c][key] (reused as P[row][key]), V[key][c]  = 48 KB.
// ---------------------------------------------------------------------------
__global__ void __launch_bounds__(256)
attn_kernel()
{
    __shared__ float QT[64][64];   // [channel][row]
    __shared__ float KT[64][64];   // [channel][key]; reused as Ps[row][key]
    __shared__ float Vs[64][64];   // [key][channel]
    float (*Ps)[64] = KT;

    int qt = blockIdx.x;           // 0..31 query tile
    int h  = blockIdx.y;           // 0..15
    int b  = blockIdx.z;           // 0..3
    int tid = threadIdx.x;
    int tx = tid & 15, ty = tid >> 4;

    const size_t base = ((size_t)b * SEQ) * D_MODEL + (size_t)h * DHEAD;
    const float* Qg = g_q + base + (size_t)qt * 64 * D_MODEL;

    // Load Q tile transposed (QT[c][row])
#pragma unroll
    for (int r = 0; r < 4; ++r) {
        int idx = tid + r * 256;       // 0..1023
        int row = idx >> 4;            // 0..63
        int c4  = (idx & 15) << 2;     // 0,4,..,60
        float4 q4 = *(const float4*)(Qg + (size_t)row * D_MODEL + c4);
        QT[c4+0][row] = q4.x; QT[c4+1][row] = q4.y;
        QT[c4+2][row] = q4.z; QT[c4+3][row] = q4.w;
    }

    float m[4], l[4], o[4][4];
#pragma unroll
    for (int j = 0; j < 4; ++j) {
        m[j] = -3.0e38f; l[j] = 0.0f;
#pragma unroll
        for (int i = 0; i < 4; ++i) o[j][i] = 0.0f;
    }

    for (int kt = 0; kt < SEQ / 64; ++kt) {
        __syncthreads();   // prior iteration done reading KT(=Ps)/Vs
        const float* Kg = g_k + base + (size_t)kt * 64 * D_MODEL;
        const float* Vg = g_v + base + (size_t)kt * 64 * D_MODEL;
#pragma unroll
        for (int r = 0; r < 4; ++r) {
            int idx = tid + r * 256;
            int key = idx >> 4;
            int c4  = (idx & 15) << 2;
            float4 k4 = *(const float4*)(Kg + (size_t)key * D_MODEL + c4);
            KT[c4+0][key] = k4.x; KT[c4+1][key] = k4.y;
            KT[c4+2][key] = k4.z; KT[c4+3][key] = k4.w;
            *(float4*)&Vs[key][c4] = *(const float4*)(Vg + (size_t)key * D_MODEL + c4);
        }
        __syncthreads();

        // S = Q @ K^T  (thread: rows 4ty+j, keys 4tx+i)
        float s[4][4];
#pragma unroll
        for (int j = 0; j < 4; ++j)
#pragma unroll
            for (int i = 0; i < 4; ++i) s[j][i] = 0.0f;

#pragma unroll 8
        for (int c = 0; c < 64; ++c) {
            float4 qv = *(const float4*)&QT[c][ty*4];
            float4 kv = *(const float4*)&KT[c][tx*4];
            float qa[4] = {qv.x, qv.y, qv.z, qv.w};
            float ka[4] = {kv.x, kv.y, kv.z, kv.w};
#pragma unroll
            for (int j = 0; j < 4; ++j)
#pragma unroll
                for (int i = 0; i < 4; ++i)
                    s[j][i] += qa[j] * ka[i];
        }

        // scale 1/sqrt(64) and online softmax
#pragma unroll
        for (int j = 0; j < 4; ++j) {
#pragma unroll
            for (int i = 0; i < 4; ++i) s[j][i] *= 0.125f;
            float rm = fmaxf(fmaxf(s[j][0], s[j][1]), fmaxf(s[j][2], s[j][3]));
#pragma unroll
            for (int off = 1; off < 16; off <<= 1)
                rm = fmaxf(rm, __shfl_xor_sync(0xffffffffu, rm, off));
            float mn = fmaxf(m[j], rm);
            float alpha = __expf(m[j] - mn);
            float rs = 0.0f;
#pragma unroll
            for (int i = 0; i < 4; ++i) {
                s[j][i] = __expf(s[j][i] - mn);
                rs += s[j][i];
            }
#pragma unroll
            for (int off = 1; off < 16; off <<= 1)
                rs += __shfl_xor_sync(0xffffffffu, rs, off);
            l[j] = l[j] * alpha + rs;
#pragma unroll
            for (int i = 0; i < 4; ++i) o[j][i] *= alpha;
            m[j] = mn;
        }

        __syncthreads();   // all S reads of KT done; safe to overwrite as Ps
#pragma unroll
        for (int j = 0; j < 4; ++j)
            *(float4*)&Ps[ty*4 + j][tx*4] =
                make_float4(s[j][0], s[j][1], s[j][2], s[j][3]);
        __syncthreads();

        // O += P @ V   (thread: rows 4ty+j, channels 4tx+i)
#pragma unroll 8
        for (int kk = 0; kk < 64; ++kk) {
            float4 vv = *(const float4*)&Vs[kk][tx*4];
            float va[4] = {vv.x, vv.y, vv.z, vv.w};
            float pj[4];
#pragma unroll
            for (int j = 0; j < 4; ++j) pj[j] = Ps[ty*4 + j][kk];
#pragma unroll
            for (int j = 0; j < 4; ++j)
#pragma unroll
                for (int i = 0; i < 4; ++i)
                    o[j][i] += pj[j] * va[i];
        }
    }

    float* Og = g_ctx + base + (size_t)qt * 64 * D_MODEL;
#pragma unroll
    for (int j = 0; j < 4; ++j) {
        float inv = 1.0f / l[j];
        float4 r = make_float4(o[j][0]*inv, o[j][1]*inv, o[j][2]*inv, o[j][3]*inv);
        *(float4*)(Og + (size_t)(ty*4 + j) * D_MODEL + tx*4) = r;
    }
}

// ---------------------------------------------------------------------------
extern "C" void kernel_launch(void* const* d_in, const int* in_sizes, int n_in,
                              void* d_out, int out_size)
{
    const float* x  = (const float*)d_in[0];
    const float* Wq = (const float*)d_in[1];
    const float* Wk = (const float*)d_in[2];
    const float* Wv = (const float*)d_in[3];
    const float* Wo = (const float*)d_in[4];
    float* out = (float*)d_out;

    dim3 gqkv(D_MODEL/128, MTOT/128, 3);
    qkv_kernel<<<gqkv, 256>>>(x, Wq, Wk, Wv);

    attn_kernel<<<dim3(SEQ/64, NHEADS, BATCH), 256>>>();

    dim3 go(D_MODEL/128, MTOT/128, 1);
    oproj_kernel<<<go, 256>>>(Wo, out);
}

// round 4
// speedup vs baseline: 3.1462x; 3.1462x over previous
#include <cuda_runtime.h>
#include <cstdint>

#define D_MODEL 1024
#define NHEADS  16
#define DHEAD   64
#define BATCH   4
#define SEQ     2048
#define MTOT    (BATCH*SEQ)   // 8192

// Scratch (static device globals — allocation-free per harness rules). 134 MB.
__device__ float g_q[MTOT*D_MODEL];
__device__ float g_k[MTOT*D_MODEL];
__device__ float g_v[MTOT*D_MODEL];
__device__ float g_ctx[MTOT*D_MODEL];

// ---------------------------------------------------------------------------
// tf32 helpers (legacy mma.sync path — works at plain sm_100 target)
// ---------------------------------------------------------------------------
__device__ __forceinline__ uint32_t f2tf32(float f) {
    uint32_t u;
    asm("cvt.rna.tf32.f32 %0, %1;" : "=r"(u) : "f"(f));
    return u;
}

__device__ __forceinline__ void mma_tf32(float* d, const uint32_t* a,
                                         uint32_t b0, uint32_t b1) {
    asm volatile(
        "mma.sync.aligned.m16n8k8.row.col.f32.tf32.tf32.f32 "
        "{%0,%1,%2,%3}, {%4,%5,%6,%7}, {%8,%9}, {%0,%1,%2,%3};"
        : "+f"(d[0]), "+f"(d[1]), "+f"(d[2]), "+f"(d[3])
        : "r"(a[0]), "r"(a[1]), "r"(a[2]), "r"(a[3]), "r"(b0), "r"(b1));
}

// ===========================================================================
// GEMM: C[M,N] = A[M,K] @ B[N,K]^T (nn.Linear), tf32 tensor cores.
// 128x128 CTA tile, BK=32, 8 warps (4x2), warp tile 32x64.
// ===========================================================================
#define GBM 128
#define GBN 128
#define GBK 32
#define ASTR 36   // smem row stride (floats): 36 mod 32 = 4 -> conflict-free frags

__device__ __forceinline__ void gemm_tf32_body(
    const float* __restrict__ A, const float* __restrict__ B,
    float* __restrict__ C)
{
    __shared__ uint32_t As[GBM * ASTR];
    __shared__ uint32_t Bs[GBN * ASTR];

    const int tid = threadIdx.x;
    const int wid = tid >> 5;
    const int lane = tid & 31;
    const int g  = lane >> 2;     // 0..7
    const int tg = lane & 3;      // 0..3
    const int wm = wid >> 1;      // 0..3
    const int wn = wid & 1;       // 0..1
    const int m0 = wm * 32;
    const int n0 = wn * 64;
    const int row0 = blockIdx.y * GBM;
    const int col0 = blockIdx.x * GBN;

    float acc[2][8][4];
#pragma unroll
    for (int mt = 0; mt < 2; ++mt)
#pragma unroll
        for (int nt = 0; nt < 8; ++nt)
#pragma unroll
            for (int i = 0; i < 4; ++i) acc[mt][nt][i] = 0.0f;

    const float* Ap = A + (size_t)row0 * D_MODEL;
    const float* Bp = B + (size_t)col0 * D_MODEL;

    for (int c = 0; c < D_MODEL / GBK; ++c) {
        if (c > 0) __syncthreads();
        // Load 128x32 tiles of A and B (1024 float4 each; 4 per thread).
#pragma unroll
        for (int r = 0; r < 4; ++r) {
            int idx = tid + r * 256;
            int row = idx >> 3;
            int k4  = (idx & 7) * 4;
            float4 a4 = *(const float4*)(Ap + (size_t)row * D_MODEL + c * GBK + k4);
            float4 b4 = *(const float4*)(Bp + (size_t)row * D_MODEL + c * GBK + k4);
            uint4 au = make_uint4(f2tf32(a4.x), f2tf32(a4.y), f2tf32(a4.z), f2tf32(a4.w));
            uint4 bu = make_uint4(f2tf32(b4.x), f2tf32(b4.y), f2tf32(b4.z), f2tf32(b4.w));
            *(uint4*)&As[row * ASTR + k4] = au;
            *(uint4*)&Bs[row * ASTR + k4] = bu;
        }
        __syncthreads();

#pragma unroll
        for (int ks = 0; ks < 4; ++ks) {
            const int k0 = ks * 8;
            uint32_t a[2][4];
#pragma unroll
            for (int mt = 0; mt < 2; ++mt) {
                const int mb = m0 + mt * 16;
                a[mt][0] = As[(mb + g)     * ASTR + k0 + tg];
                a[mt][1] = As[(mb + g + 8) * ASTR + k0 + tg];
                a[mt][2] = As[(mb + g)     * ASTR + k0 + tg + 4];
                a[mt][3] = As[(mb + g + 8) * ASTR + k0 + tg + 4];
            }
#pragma unroll
            for (int nt = 0; nt < 8; ++nt) {
                uint32_t b0 = Bs[(n0 + nt * 8 + g) * ASTR + k0 + tg];
                uint32_t b1 = Bs[(n0 + nt * 8 + g) * ASTR + k0 + tg + 4];
                mma_tf32(acc[0][nt], a[0], b0, b1);
                mma_tf32(acc[1][nt], a[1], b0, b1);
            }
        }
    }

    // Epilogue: float2 stores per fragment half-row.
#pragma unroll
    for (int mt = 0; mt < 2; ++mt) {
        const int rbase = row0 + m0 + mt * 16 + g;
#pragma unroll
        for (int nt = 0; nt < 8; ++nt) {
            const int col = col0 + n0 + nt * 8 + 2 * tg;
            *(float2*)(C + (size_t)rbase * D_MODEL + col) =
                make_float2(acc[mt][nt][0], acc[mt][nt][1]);
            *(float2*)(C + (size_t)(rbase + 8) * D_MODEL + col) =
                make_float2(acc[mt][nt][2], acc[mt][nt][3]);
        }
    }
}

__global__ void __launch_bounds__(256, 2)
qkv_tc_kernel(const float* __restrict__ x,
              const float* __restrict__ Wq,
              const float* __restrict__ Wk,
              const float* __restrict__ Wv)
{
    const float* W;
    float* out;
    if (blockIdx.z == 0)      { W = Wq; out = g_q; }
    else if (blockIdx.z == 1) { W = Wk; out = g_k; }
    else                      { W = Wv; out = g_v; }
    gemm_tf32_body(x, W, out);
}

__global__ void __launch_bounds__(256, 2)
oproj_tc_kernel(const float* __restrict__ Wo, float* __restrict__ out)
{
    gemm_tf32_body(g_ctx, Wo, out);
}

// ===========================================================================
// Flash attention, tf32 tensor cores.
// CTA = (64-query tile, head, batch), 128 threads (4 warps, 16 q-rows each).
// K tile smem reused for P between the S and PV matmuls.
// ===========================================================================
#define KSTR 68   // 68 mod 32 = 4 -> conflict-free fragment loads

__global__ void __launch_bounds__(128)
attn_tc_kernel()
{
    __shared__ uint32_t Ks[64 * KSTR];   // K tile [key][ch]; reused as P [qrow][key]
    __shared__ uint32_t Vs[64 * KSTR];   // V tile transposed [ch][key]

    const int qt = blockIdx.x;
    const int h  = blockIdx.y;
    const int b  = blockIdx.z;
    const int tid  = threadIdx.x;
    const int w    = tid >> 5;
    const int lane = tid & 31;
    const int g  = lane >> 2;
    const int tg = lane & 3;
    const int qr = w * 16;               // warp's query-row base within tile

    const float* Qg = g_q + (size_t)(b * SEQ + qt * 64) * D_MODEL + h * DHEAD;
    const float* Kb = g_k + (size_t)(b * SEQ) * D_MODEL + h * DHEAD;
    const float* Vb = g_v + (size_t)(b * SEQ) * D_MODEL + h * DHEAD;

    // Preload Q fragments (scaled into tf32 once): 8 k-steps x 4 regs.
    uint32_t qf[8][4];
#pragma unroll
    for (int ks = 0; ks < 8; ++ks) {
        const int k0 = ks * 8;
        qf[ks][0] = f2tf32(Qg[(size_t)(qr + g)     * D_MODEL + k0 + tg]);
        qf[ks][1] = f2tf32(Qg[(size_t)(qr + g + 8) * D_MODEL + k0 + tg]);
        qf[ks][2] = f2tf32(Qg[(size_t)(qr + g)     * D_MODEL + k0 + tg + 4]);
        qf[ks][3] = f2tf32(Qg[(size_t)(qr + g + 8) * D_MODEL + k0 + tg + 4]);
    }

    float of[8][4];
#pragma unroll
    for (int nt = 0; nt < 8; ++nt)
#pragma unroll
        for (int i = 0; i < 4; ++i) of[nt][i] = 0.0f;
    float m0 = -3.0e38f, m1 = -3.0e38f, l0 = 0.0f, l1 = 0.0f;

    for (int kt = 0; kt < SEQ / 64; ++kt) {
        __syncthreads();   // previous PV done with Ks(=P)/Vs
        const float* Kg = Kb + (size_t)kt * 64 * D_MODEL;
        const float* Vg = Vb + (size_t)kt * 64 * D_MODEL;
#pragma unroll
        for (int r = 0; r < 8; ++r) {
            int idx = tid + r * 128;
            int key = idx >> 4;
            int c4  = (idx & 15) * 4;
            float4 k4 = *(const float4*)(Kg + (size_t)key * D_MODEL + c4);
            *(uint4*)&Ks[key * KSTR + c4] =
                make_uint4(f2tf32(k4.x), f2tf32(k4.y), f2tf32(k4.z), f2tf32(k4.w));
            float4 v4 = *(const float4*)(Vg + (size_t)key * D_MODEL + c4);
            Vs[(c4 + 0) * KSTR + key] = f2tf32(v4.x);
            Vs[(c4 + 1) * KSTR + key] = f2tf32(v4.y);
            Vs[(c4 + 2) * KSTR + key] = f2tf32(v4.z);
            Vs[(c4 + 3) * KSTR + key] = f2tf32(v4.w);
        }
        __syncthreads();

        // S = Q @ K^T : 8 k-steps x 8 key-tiles
        float sf[8][4];
#pragma unroll
        for (int nt = 0; nt < 8; ++nt)
#pragma unroll
            for (int i = 0; i < 4; ++i) sf[nt][i] = 0.0f;
#pragma unroll
        for (int ks = 0; ks < 8; ++ks) {
            const int k0 = ks * 8;
#pragma unroll
            for (int nt = 0; nt < 8; ++nt) {
                uint32_t b0 = Ks[(nt * 8 + g) * KSTR + k0 + tg];
                uint32_t b1 = Ks[(nt * 8 + g) * KSTR + k0 + tg + 4];
                mma_tf32(sf[nt], qf[ks], b0, b1);
            }
        }

        // Scale + online softmax. Thread's rows: g (sf[.][0..1]) and g+8 (sf[.][2..3]).
        float rm0 = -3.0e38f, rm1 = -3.0e38f;
#pragma unroll
        for (int nt = 0; nt < 8; ++nt) {
            sf[nt][0] *= 0.125f; sf[nt][1] *= 0.125f;
            sf[nt][2] *= 0.125f; sf[nt][3] *= 0.125f;
            rm0 = fmaxf(rm0, fmaxf(sf[nt][0], sf[nt][1]));
            rm1 = fmaxf(rm1, fmaxf(sf[nt][2], sf[nt][3]));
        }
        rm0 = fmaxf(rm0, __shfl_xor_sync(0xffffffffu, rm0, 1));
        rm0 = fmaxf(rm0, __shfl_xor_sync(0xffffffffu, rm0, 2));
        rm1 = fmaxf(rm1, __shfl_xor_sync(0xffffffffu, rm1, 1));
        rm1 = fmaxf(rm1, __shfl_xor_sync(0xffffffffu, rm1, 2));
        const float mn0 = fmaxf(m0, rm0), mn1 = fmaxf(m1, rm1);
        const float al0 = __expf(m0 - mn0), al1 = __expf(m1 - mn1);
        float rs0 = 0.0f, rs1 = 0.0f;
#pragma unroll
        for (int nt = 0; nt < 8; ++nt) {
            sf[nt][0] = __expf(sf[nt][0] - mn0); rs0 += sf[nt][0];
            sf[nt][1] = __expf(sf[nt][1] - mn0); rs0 += sf[nt][1];
            sf[nt][2] = __expf(sf[nt][2] - mn1); rs1 += sf[nt][2];
            sf[nt][3] = __expf(sf[nt][3] - mn1); rs1 += sf[nt][3];
        }
        rs0 += __shfl_xor_sync(0xffffffffu, rs0, 1);
        rs0 += __shfl_xor_sync(0xffffffffu, rs0, 2);
        rs1 += __shfl_xor_sync(0xffffffffu, rs1, 1);
        rs1 += __shfl_xor_sync(0xffffffffu, rs1, 2);
        l0 = l0 * al0 + rs0;
        l1 = l1 * al1 + rs1;
#pragma unroll
        for (int nt = 0; nt < 8; ++nt) {
            of[nt][0] *= al0; of[nt][1] *= al0;
            of[nt][2] *= al1; of[nt][3] *= al1;
        }
        m0 = mn0; m1 = mn1;

        __syncthreads();   // all warps done reading Ks; reuse as P
#pragma unroll
        for (int nt = 0; nt < 8; ++nt) {
            const int col = nt * 8 + 2 * tg;
            *(uint2*)&Ks[(qr + g) * KSTR + col] =
                make_uint2(f2tf32(sf[nt][0]), f2tf32(sf[nt][1]));
            *(uint2*)&Ks[(qr + g + 8) * KSTR + col] =
                make_uint2(f2tf32(sf[nt][2]), f2tf32(sf[nt][3]));
        }
        __syncthreads();

        // O += P @ V : 8 k-steps (keys) x 8 channel-tiles
#pragma unroll
        for (int ks = 0; ks < 8; ++ks) {
            const int kk0 = ks * 8;
            uint32_t pa[4];
            pa[0] = Ks[(qr + g)     * KSTR + kk0 + tg];
            pa[1] = Ks[(qr + g + 8) * KSTR + kk0 + tg];
            pa[2] = Ks[(qr + g)     * KSTR + kk0 + tg + 4];
            pa[3] = Ks[(qr + g + 8) * KSTR + kk0 + tg + 4];
#pragma unroll
            for (int nt = 0; nt < 8; ++nt) {
                uint32_t b0 = Vs[(nt * 8 + g) * KSTR + kk0 + tg];
                uint32_t b1 = Vs[(nt * 8 + g) * KSTR + kk0 + tg + 4];
                mma_tf32(of[nt], pa, b0, b1);
            }
        }
    }

    // Normalize and write context.
    const float inv0 = 1.0f / l0, inv1 = 1.0f / l1;
    float* Og = g_ctx + (size_t)(b * SEQ + qt * 64) * D_MODEL + h * DHEAD;
#pragma unroll
    for (int nt = 0; nt < 8; ++nt) {
        const int col = nt * 8 + 2 * tg;
        *(float2*)(Og + (size_t)(qr + g) * D_MODEL + col) =
            make_float2(of[nt][0] * inv0, of[nt][1] * inv0);
        *(float2*)(Og + (size_t)(qr + g + 8) * D_MODEL + col) =
            make_float2(of[nt][2] * inv1, of[nt][3] * inv1);
    }
}

// ---------------------------------------------------------------------------
extern "C" void kernel_launch(void* const* d_in, const int* in_sizes, int n_in,
                              void* d_out, int out_size)
{
    const float* x  = (const float*)d_in[0];
    const float* Wq = (const float*)d_in[1];
    const float* Wk = (const float*)d_in[2];
    const float* Wv = (const float*)d_in[3];
    const float* Wo = (const float*)d_in[4];
    float* out = (float*)d_out;

    dim3 gqkv(D_MODEL / GBN, MTOT / GBM, 3);
    qkv_tc_kernel<<<gqkv, 256>>>(x, Wq, Wk, Wv);

    attn_tc_kernel<<<dim3(SEQ / 64, NHEADS, BATCH), 128>>>();

    dim3 go(D_MODEL / GBN, MTOT / GBM, 1);
    oproj_tc_kernel<<<go, 256>>>(Wo, out);
}

// round 6
// speedup vs baseline: 5.7752x; 1.8356x over previous
#include <cuda_runtime.h>
#include <cuda_fp16.h>
#include <cstdint>

#define D_MODEL 1024
#define NHEADS  16
#define DHEAD   64
#define BATCH   4
#define SEQ     2048
#define MTOT    (BATCH*SEQ)   // 8192

// Scratch (static device globals — allocation-free per harness rules). 134 MB.
__device__ float g_q[MTOT*D_MODEL];
__device__ float g_k[MTOT*D_MODEL];
__device__ float g_v[MTOT*D_MODEL];
__device__ float g_ctx[MTOT*D_MODEL];

// ---------------------------------------------------------------------------
// helpers
// ---------------------------------------------------------------------------
__device__ __forceinline__ uint32_t smem_u32(const void* p) {
    uint32_t a;
    asm("{ .reg .u64 t; cvta.to.shared.u64 t, %1; cvt.u32.u64 %0, t; }"
        : "=r"(a) : "l"(p));
    return a;
}
__device__ __forceinline__ uint32_t packh2(float lo, float hi) {
    __half2 h = __floats2half2_rn(lo, hi);
    return *reinterpret_cast<uint32_t*>(&h);
}
__device__ __forceinline__ void ldsm4(uint32_t addr, uint32_t* r) {
    asm volatile("ldmatrix.sync.aligned.m8n8.x4.shared.b16 {%0,%1,%2,%3}, [%4];"
        : "=r"(r[0]), "=r"(r[1]), "=r"(r[2]), "=r"(r[3]) : "r"(addr));
}
__device__ __forceinline__ void ldsm4t(uint32_t addr, uint32_t* r) {
    asm volatile("ldmatrix.sync.aligned.m8n8.x4.trans.shared.b16 {%0,%1,%2,%3}, [%4];"
        : "=r"(r[0]), "=r"(r[1]), "=r"(r[2]), "=r"(r[3]) : "r"(addr));
}
__device__ __forceinline__ void mma_f16(float* d, const uint32_t* a,
                                        uint32_t b0, uint32_t b1) {
    asm volatile(
        "mma.sync.aligned.m16n8k16.row.col.f32.f16.f16.f32 "
        "{%0,%1,%2,%3}, {%4,%5,%6,%7}, {%8,%9}, {%0,%1,%2,%3};"
        : "+f"(d[0]), "+f"(d[1]), "+f"(d[2]), "+f"(d[3])
        : "r"(a[0]), "r"(a[1]), "r"(a[2]), "r"(a[3]), "r"(b0), "r"(b1));
}

// ===========================================================================
// GEMM: C[M,N] = A[M,K] @ B[N,K]^T (nn.Linear), fp16 m16n8k16 tensor cores.
// 128x128 CTA tile, BK=32, 8 warps (4x2), warp tile 32x64. ldmatrix frags.
// ===========================================================================
#define GSTR 40   // smem row stride in halves (80B): conflict-free ldmatrix

__device__ __forceinline__ void gemm_f16_body(
    const float* __restrict__ A, const float* __restrict__ B,
    float* __restrict__ C)
{
    __shared__ __half As[128 * GSTR];
    __shared__ __half Bs[128 * GSTR];

    const int tid = threadIdx.x;
    const int wid = tid >> 5;
    const int lane = tid & 31;
    const int g  = lane >> 2;
    const int tg = lane & 3;
    const int mi = lane >> 3, ri = lane & 7;
    const int m0 = (wid >> 1) * 32;
    const int n0 = (wid & 1) * 64;
    const int row0 = blockIdx.y * 128;
    const int col0 = blockIdx.x * 128;

    const uint32_t sA = smem_u32(As), sB = smem_u32(Bs);
    // per-lane ldmatrix row offsets (in halves)
    const uint32_t a_lane = (uint32_t)(((mi & 1) * 8 + ri) * GSTR + (mi >> 1) * 8);
    const uint32_t b_lane = (uint32_t)(((mi >> 1) * 8 + ri) * GSTR + (mi & 1) * 8);

    float acc[2][8][4];
#pragma unroll
    for (int mt = 0; mt < 2; ++mt)
#pragma unroll
        for (int nt = 0; nt < 8; ++nt)
#pragma unroll
            for (int i = 0; i < 4; ++i) acc[mt][nt][i] = 0.0f;

    const float* Ap = A + (size_t)row0 * D_MODEL;
    const float* Bp = B + (size_t)col0 * D_MODEL;

    for (int c = 0; c < D_MODEL / 32; ++c) {
        if (c > 0) __syncthreads();
#pragma unroll
        for (int r = 0; r < 4; ++r) {
            int idx = tid + r * 256;
            int row = idx >> 3;
            int k4  = (idx & 7) * 4;
            float4 a4 = *(const float4*)(Ap + (size_t)row * D_MODEL + c * 32 + k4);
            float4 b4 = *(const float4*)(Bp + (size_t)row * D_MODEL + c * 32 + k4);
            *(uint32_t*)&As[row * GSTR + k4]     = packh2(a4.x, a4.y);
            *(uint32_t*)&As[row * GSTR + k4 + 2] = packh2(a4.z, a4.w);
            *(uint32_t*)&Bs[row * GSTR + k4]     = packh2(b4.x, b4.y);
            *(uint32_t*)&Bs[row * GSTR + k4 + 2] = packh2(b4.z, b4.w);
        }
        __syncthreads();

#pragma unroll
        for (int kc = 0; kc < 2; ++kc) {
            uint32_t a[2][4];
            ldsm4(sA + 2 * ((uint32_t)(m0 * GSTR + kc * 16) + a_lane), a[0]);
            ldsm4(sA + 2 * ((uint32_t)((m0 + 16) * GSTR + kc * 16) + a_lane), a[1]);
#pragma unroll
            for (int ntp = 0; ntp < 4; ++ntp) {
                uint32_t b[4];
                ldsm4(sB + 2 * ((uint32_t)((n0 + ntp * 16) * GSTR + kc * 16) + b_lane), b);
                mma_f16(acc[0][2 * ntp],     a[0], b[0], b[1]);
                mma_f16(acc[0][2 * ntp + 1], a[0], b[2], b[3]);
                mma_f16(acc[1][2 * ntp],     a[1], b[0], b[1]);
                mma_f16(acc[1][2 * ntp + 1], a[1], b[2], b[3]);
            }
        }
    }

#pragma unroll
    for (int mt = 0; mt < 2; ++mt) {
        const int rbase = row0 + m0 + mt * 16 + g;
#pragma unroll
        for (int nt = 0; nt < 8; ++nt) {
            const int col = col0 + n0 + nt * 8 + 2 * tg;
            *(float2*)(C + (size_t)rbase * D_MODEL + col) =
                make_float2(acc[mt][nt][0], acc[mt][nt][1]);
            *(float2*)(C + (size_t)(rbase + 8) * D_MODEL + col) =
                make_float2(acc[mt][nt][2], acc[mt][nt][3]);
        }
    }
}

__global__ void __launch_bounds__(256, 2)
qkv_tc_kernel(const float* __restrict__ x,
              const float* __restrict__ Wq,
              const float* __restrict__ Wk,
              const float* __restrict__ Wv)
{
    const float* W;
    float* out;
    if (blockIdx.z == 0)      { W = Wq; out = g_q; }
    else if (blockIdx.z == 1) { W = Wk; out = g_k; }
    else                      { W = Wv; out = g_v; }
    gemm_f16_body(x, W, out);
}

__global__ void __launch_bounds__(256, 2)
oproj_tc_kernel(const float* __restrict__ Wo, float* __restrict__ out)
{
    gemm_f16_body(g_ctx, Wo, out);
}

// ===========================================================================
// Flash attention, fp16 m16n8k16, FA2-style register-resident P.
// CTA = (128-query tile, head, batch), 128 threads, 4 warps x 32 q-rows.
// K stored [key][ch] (ldmatrix), V stored [key][ch] (ldmatrix.trans).
// ===========================================================================
#define KST 72   // smem row stride in halves (144B): conflict-free ldmatrix

__global__ void __launch_bounds__(128, 2)
attn_f16_kernel()
{
    __shared__ __half Ks[64 * KST];
    __shared__ __half Vs[64 * KST];

    const int qt = blockIdx.x;
    const int h  = blockIdx.y;
    const int b  = blockIdx.z;
    const int tid  = threadIdx.x;
    const int w    = tid >> 5;
    const int lane = tid & 31;
    const int g  = lane >> 2;
    const int tg = lane & 3;
    const int mi = lane >> 3, ri = lane & 7;
    const int qr = w * 32;               // warp's query-row base within 128-tile

    const uint32_t sK = smem_u32(Ks), sV = smem_u32(Vs);
    // K b-frag: matrix rows = keys, 16B chunks = channels
    const uint32_t kb_lane = (uint32_t)(((mi >> 1) * 8 + ri) * KST + (mi & 1) * 8);
    // V trans b-frag: matrix rows = keys (k), cols = channels (n)
    const uint32_t vb_lane = (uint32_t)(((mi & 1) * 8 + ri) * KST + (mi >> 1) * 8);

    const float* Qg = g_q + (size_t)(b * SEQ + qt * 128) * D_MODEL + h * DHEAD;
    const float* Kb = g_k + (size_t)(b * SEQ) * D_MODEL + h * DHEAD;
    const float* Vb = g_v + (size_t)(b * SEQ) * D_MODEL + h * DHEAD;

    // Preload Q a-frags with softmax scale folded in (exact: *0.125).
    uint32_t qf[2][4][4];
#pragma unroll
    for (int mt = 0; mt < 2; ++mt)
#pragma unroll
        for (int kc = 0; kc < 4; ++kc) {
            const float* q0 = Qg + (size_t)(qr + mt * 16 + g) * D_MODEL + kc * 16 + 2 * tg;
            const float* q1 = Qg + (size_t)(qr + mt * 16 + g + 8) * D_MODEL + kc * 16 + 2 * tg;
            float2 x0 = *(const float2*)q0;
            float2 x1 = *(const float2*)q1;
            float2 x2 = *(const float2*)(q0 + 8);
            float2 x3 = *(const float2*)(q1 + 8);
            qf[mt][kc][0] = packh2(x0.x * 0.125f, x0.y * 0.125f);
            qf[mt][kc][1] = packh2(x1.x * 0.125f, x1.y * 0.125f);
            qf[mt][kc][2] = packh2(x2.x * 0.125f, x2.y * 0.125f);
            qf[mt][kc][3] = packh2(x3.x * 0.125f, x3.y * 0.125f);
        }

    float of[2][8][4];
#pragma unroll
    for (int mt = 0; mt < 2; ++mt)
#pragma unroll
        for (int nt = 0; nt < 8; ++nt)
#pragma unroll
            for (int i = 0; i < 4; ++i) of[mt][nt][i] = 0.0f;
    float mrow[2][2], lrow[2][2];
#pragma unroll
    for (int mt = 0; mt < 2; ++mt) {
        mrow[mt][0] = -3.0e38f; mrow[mt][1] = -3.0e38f;
        lrow[mt][0] = 0.0f;     lrow[mt][1] = 0.0f;
    }

    for (int kt = 0; kt < SEQ / 64; ++kt) {
        __syncthreads();   // previous iteration done reading Ks/Vs
        const float* Kg = Kb + (size_t)kt * 64 * D_MODEL;
        const float* Vg = Vb + (size_t)kt * 64 * D_MODEL;
#pragma unroll
        for (int r = 0; r < 8; ++r) {
            int idx = tid + r * 128;
            int row = idx >> 4;
            int c4  = (idx & 15) * 4;
            float4 k4 = *(const float4*)(Kg + (size_t)row * D_MODEL + c4);
            float4 v4 = *(const float4*)(Vg + (size_t)row * D_MODEL + c4);
            *(uint32_t*)&Ks[row * KST + c4]     = packh2(k4.x, k4.y);
            *(uint32_t*)&Ks[row * KST + c4 + 2] = packh2(k4.z, k4.w);
            *(uint32_t*)&Vs[row * KST + c4]     = packh2(v4.x, v4.y);
            *(uint32_t*)&Vs[row * KST + c4 + 2] = packh2(v4.z, v4.w);
        }
        __syncthreads();

        // ---- S = (Q*0.125) @ K^T ----
        float sf[2][8][4];
#pragma unroll
        for (int mt = 0; mt < 2; ++mt)
#pragma unroll
            for (int nt = 0; nt < 8; ++nt)
#pragma unroll
                for (int i = 0; i < 4; ++i) sf[mt][nt][i] = 0.0f;

#pragma unroll
        for (int kc = 0; kc < 4; ++kc) {
#pragma unroll
            for (int ntp = 0; ntp < 4; ++ntp) {
                uint32_t bf[4];
                ldsm4(sK + 2 * ((uint32_t)(ntp * 16 * KST + kc * 16) + kb_lane), bf);
                mma_f16(sf[0][2 * ntp],     qf[0][kc], bf[0], bf[1]);
                mma_f16(sf[0][2 * ntp + 1], qf[0][kc], bf[2], bf[3]);
                mma_f16(sf[1][2 * ntp],     qf[1][kc], bf[0], bf[1]);
                mma_f16(sf[1][2 * ntp + 1], qf[1][kc], bf[2], bf[3]);
            }
        }

        // ---- online softmax (rows g and g+8 per m-tile) ----
        uint32_t pa[2][4][4];
#pragma unroll
        for (int mt = 0; mt < 2; ++mt) {
            float rm0 = -3.0e38f, rm1 = -3.0e38f;
#pragma unroll
            for (int nt = 0; nt < 8; ++nt) {
                rm0 = fmaxf(rm0, fmaxf(sf[mt][nt][0], sf[mt][nt][1]));
                rm1 = fmaxf(rm1, fmaxf(sf[mt][nt][2], sf[mt][nt][3]));
            }
            rm0 = fmaxf(rm0, __shfl_xor_sync(0xffffffffu, rm0, 1));
            rm0 = fmaxf(rm0, __shfl_xor_sync(0xffffffffu, rm0, 2));
            rm1 = fmaxf(rm1, __shfl_xor_sync(0xffffffffu, rm1, 1));
            rm1 = fmaxf(rm1, __shfl_xor_sync(0xffffffffu, rm1, 2));
            const float mn0 = fmaxf(mrow[mt][0], rm0);
            const float mn1 = fmaxf(mrow[mt][1], rm1);
            const float al0 = __expf(mrow[mt][0] - mn0);
            const float al1 = __expf(mrow[mt][1] - mn1);
            float rs0 = 0.0f, rs1 = 0.0f;
#pragma unroll
            for (int nt = 0; nt < 8; ++nt) {
                sf[mt][nt][0] = __expf(sf[mt][nt][0] - mn0); rs0 += sf[mt][nt][0];
                sf[mt][nt][1] = __expf(sf[mt][nt][1] - mn0); rs0 += sf[mt][nt][1];
                sf[mt][nt][2] = __expf(sf[mt][nt][2] - mn1); rs1 += sf[mt][nt][2];
                sf[mt][nt][3] = __expf(sf[mt][nt][3] - mn1); rs1 += sf[mt][nt][3];
            }
            rs0 += __shfl_xor_sync(0xffffffffu, rs0, 1);
            rs0 += __shfl_xor_sync(0xffffffffu, rs0, 2);
            rs1 += __shfl_xor_sync(0xffffffffu, rs1, 1);
            rs1 += __shfl_xor_sync(0xffffffffu, rs1, 2);
            lrow[mt][0] = lrow[mt][0] * al0 + rs0;
            lrow[mt][1] = lrow[mt][1] * al1 + rs1;
#pragma unroll
            for (int nt = 0; nt < 8; ++nt) {
                of[mt][nt][0] *= al0; of[mt][nt][1] *= al0;
                of[mt][nt][2] *= al1; of[mt][nt][3] *= al1;
            }
            mrow[mt][0] = mn0; mrow[mt][1] = mn1;
            // P a-frags directly from S C-frags (FA2 layout identity)
#pragma unroll
            for (int kc = 0; kc < 4; ++kc) {
                pa[mt][kc][0] = packh2(sf[mt][2 * kc][0],     sf[mt][2 * kc][1]);
                pa[mt][kc][1] = packh2(sf[mt][2 * kc][2],     sf[mt][2 * kc][3]);
                pa[mt][kc][2] = packh2(sf[mt][2 * kc + 1][0], sf[mt][2 * kc + 1][1]);
                pa[mt][kc][3] = packh2(sf[mt][2 * kc + 1][2], sf[mt][2 * kc + 1][3]);
            }
        }

        // ---- O += P @ V ----
#pragma unroll
        for (int kc = 0; kc < 4; ++kc) {
#pragma unroll
            for (int ntp = 0; ntp < 4; ++ntp) {
                uint32_t bf[4];
                ldsm4t(sV + 2 * ((uint32_t)(kc * 16 * KST + ntp * 16) + vb_lane), bf);
                mma_f16(of[0][2 * ntp],     pa[0][kc], bf[0], bf[1]);
                mma_f16(of[0][2 * ntp + 1], pa[0][kc], bf[2], bf[3]);
                mma_f16(of[1][2 * ntp],     pa[1][kc], bf[0], bf[1]);
                mma_f16(of[1][2 * ntp + 1], pa[1][kc], bf[2], bf[3]);
            }
        }
    }

    // Normalize and write context.
    float* Og = g_ctx + (size_t)(b * SEQ + qt * 128) * D_MODEL + h * DHEAD;
#pragma unroll
    for (int mt = 0; mt < 2; ++mt) {
        const float inv0 = 1.0f / lrow[mt][0];
        const float inv1 = 1.0f / lrow[mt][1];
        const int r0 = qr + mt * 16 + g;
#pragma unroll
        for (int nt = 0; nt < 8; ++nt) {
            const int col = nt * 8 + 2 * tg;
            *(float2*)(Og + (size_t)r0 * D_MODEL + col) =
                make_float2(of[mt][nt][0] * inv0, of[mt][nt][1] * inv0);
            *(float2*)(Og + (size_t)(r0 + 8) * D_MODEL + col) =
                make_float2(of[mt][nt][2] * inv1, of[mt][nt][3] * inv1);
        }
    }
}

// ---------------------------------------------------------------------------
extern "C" void kernel_launch(void* const* d_in, const int* in_sizes, int n_in,
                              void* d_out, int out_size)
{
    const float* x  = (const float*)d_in[0];
    const float* Wq = (const float*)d_in[1];
    const float* Wk = (const float*)d_in[2];
    const float* Wv = (const float*)d_in[3];
    const float* Wo = (const float*)d_in[4];
    float* out = (float*)d_out;

    dim3 gqkv(D_MODEL / 128, MTOT / 128, 3);
    qkv_tc_kernel<<<gqkv, 256>>>(x, Wq, Wk, Wv);

    attn_f16_kernel<<<dim3(SEQ / 128, NHEADS, BATCH), 128>>>();

    dim3 go(D_MODEL / 128, MTOT / 128, 1);
    oproj_tc_kernel<<<go, 256>>>(Wo, out);
}

// round 8
// speedup vs baseline: 7.2871x; 1.2618x over previous
#include <cuda_runtime.h>
#include <cuda_fp16.h>
#include <cstdint>

#define D_MODEL 1024
#define NHEADS  16
#define DHEAD   64
#define BATCH   4
#define SEQ     2048
#define MTOT    (BATCH*SEQ)   // 8192

// fp16 scratch (static device globals — allocation-free per harness rules).
__device__ __half g_xh[MTOT*D_MODEL];
__device__ __half g_wq[D_MODEL*D_MODEL];
__device__ __half g_wk[D_MODEL*D_MODEL];
__device__ __half g_wv[D_MODEL*D_MODEL];
__device__ __half g_wo[D_MODEL*D_MODEL];
__device__ __half g_qh[MTOT*D_MODEL];    // pre-scaled by 0.125
__device__ __half g_kh[MTOT*D_MODEL];
__device__ __half g_vh[MTOT*D_MODEL];
__device__ __half g_ctxh[MTOT*D_MODEL];

// ---------------------------------------------------------------------------
// helpers
// ---------------------------------------------------------------------------
__device__ __forceinline__ uint32_t smem_u32(const void* p) {
    uint32_t a;
    asm("{ .reg .u64 t; cvta.to.shared.u64 t, %1; cvt.u32.u64 %0, t; }"
        : "=r"(a) : "l"(p));
    return a;
}
__device__ __forceinline__ uint32_t packh2(float lo, float hi) {
    __half2 h = __floats2half2_rn(lo, hi);
    return *reinterpret_cast<uint32_t*>(&h);
}
__device__ __forceinline__ void ldsm4(uint32_t addr, uint32_t* r) {
    asm volatile("ldmatrix.sync.aligned.m8n8.x4.shared.b16 {%0,%1,%2,%3}, [%4];"
        : "=r"(r[0]), "=r"(r[1]), "=r"(r[2]), "=r"(r[3]) : "r"(addr));
}
__device__ __forceinline__ void ldsm4t(uint32_t addr, uint32_t* r) {
    asm volatile("ldmatrix.sync.aligned.m8n8.x4.trans.shared.b16 {%0,%1,%2,%3}, [%4];"
        : "=r"(r[0]), "=r"(r[1]), "=r"(r[2]), "=r"(r[3]) : "r"(addr));
}
__device__ __forceinline__ void mma_f16(float* d, const uint32_t* a,
                                        uint32_t b0, uint32_t b1) {
    asm volatile(
        "mma.sync.aligned.m16n8k16.row.col.f32.f16.f16.f32 "
        "{%0,%1,%2,%3}, {%4,%5,%6,%7}, {%8,%9}, {%0,%1,%2,%3};"
        : "+f"(d[0]), "+f"(d[1]), "+f"(d[2]), "+f"(d[3])
        : "r"(a[0]), "r"(a[1]), "r"(a[2]), "r"(a[3]), "r"(b0), "r"(b1));
}
#define CP_ASYNC16(dst, src) \
    asm volatile("cp.async.cg.shared.global [%0], [%1], 16;" \
        :: "r"(dst), "l"(src))
#define CP_COMMIT() asm volatile("cp.async.commit_group;" ::: "memory")
#define CP_WAIT(n)  asm volatile("cp.async.wait_group %0;" :: "n"(n) : "memory")

// ---------------------------------------------------------------------------
// fp32 -> fp16 conversion kernels (one-time, ~24MB traffic)
// ---------------------------------------------------------------------------
__global__ void __launch_bounds__(256)
cvt_x_kernel(const float* __restrict__ x)
{
    // MTOT*D_MODEL/4 = 2097152 float4 = 1024 blocks * 256 threads * 8
    int base = (blockIdx.x * 256 + threadIdx.x) * 8;
#pragma unroll
    for (int i = 0; i < 8; ++i) {
        int idx = base + i;
        float4 v = *(const float4*)(x + (size_t)idx * 4);
        *(uint2*)(g_xh + (size_t)idx * 4) =
            make_uint2(packh2(v.x, v.y), packh2(v.z, v.w));
    }
}
__global__ void __launch_bounds__(256)
cvt_w_kernel(const float* __restrict__ Wq, const float* __restrict__ Wk,
             const float* __restrict__ Wv, const float* __restrict__ Wo)
{
    const float* src;
    __half* dst;
    switch (blockIdx.y) {
        case 0: src = Wq; dst = g_wq; break;
        case 1: src = Wk; dst = g_wk; break;
        case 2: src = Wv; dst = g_wv; break;
        default: src = Wo; dst = g_wo; break;
    }
    // D_MODEL*D_MODEL/4 = 262144 float4 = 256 blocks * 256 threads * 4
    int base = (blockIdx.x * 256 + threadIdx.x) * 4;
#pragma unroll
    for (int i = 0; i < 4; ++i) {
        int idx = base + i;
        float4 v = *(const float4*)(src + (size_t)idx * 4);
        *(uint2*)(dst + (size_t)idx * 4) =
            make_uint2(packh2(v.x, v.y), packh2(v.z, v.w));
    }
}

// ===========================================================================
// GEMM: C[M,N] = A[M,K] @ B[N,K]^T, fp16 in, cp.async double-buffered.
// 128x128 CTA tile, BK=32, 8 warps (4x2), warp tile 32x64.
// ===========================================================================
#define GSTR 40   // smem row stride in halves (80B, 16B-aligned rows)

template<bool HALF_OUT>
__device__ __forceinline__ void gemm_f16_body(
    const __half* __restrict__ A, const __half* __restrict__ B,
    void* __restrict__ Cout, float scale)
{
    __shared__ __align__(16) __half As[2][128 * GSTR];
    __shared__ __align__(16) __half Bs[2][128 * GSTR];

    const int tid = threadIdx.x;
    const int wid = tid >> 5;
    const int lane = tid & 31;
    const int g  = lane >> 2;
    const int tg = lane & 3;
    const int mi = lane >> 3, ri = lane & 7;
    const int m0 = (wid >> 1) * 32;
    const int n0 = (wid & 1) * 64;
    const int row0 = blockIdx.y * 128;
    const int col0 = blockIdx.x * 128;

    const uint32_t sA[2] = { smem_u32(As[0]), smem_u32(As[1]) };
    const uint32_t sB[2] = { smem_u32(Bs[0]), smem_u32(Bs[1]) };
    const uint32_t a_lane = (uint32_t)(((mi & 1) * 8 + ri) * GSTR + (mi >> 1) * 8);
    const uint32_t b_lane = (uint32_t)(((mi >> 1) * 8 + ri) * GSTR + (mi & 1) * 8);

    const __half* Ap = A + (size_t)row0 * D_MODEL;
    const __half* Bp = B + (size_t)col0 * D_MODEL;

    // fill: 512 cp.async16 per operand, 4 per thread
    auto fill = [&](int c, int buf) {
#pragma unroll
        for (int r = 0; r < 4; ++r) {
            int idx = tid + r * 256;
            int op  = idx >> 9;
            int i   = idx & 511;
            int row = i >> 2;
            int seg = i & 3;
            const __half* src = (op ? Bp : Ap) + (size_t)row * D_MODEL + c * 32 + seg * 8;
            uint32_t dst = (op ? sB[buf] : sA[buf]) + (uint32_t)(row * GSTR + seg * 8) * 2;
            CP_ASYNC16(dst, src);
        }
    };

    float acc[2][8][4];
#pragma unroll
    for (int mt = 0; mt < 2; ++mt)
#pragma unroll
        for (int nt = 0; nt < 8; ++nt)
#pragma unroll
            for (int i = 0; i < 4; ++i) acc[mt][nt][i] = 0.0f;

    fill(0, 0); CP_COMMIT();

    for (int c = 0; c < D_MODEL / 32; ++c) {
        const int buf = c & 1;
        if (c + 1 < D_MODEL / 32) {
            fill(c + 1, buf ^ 1); CP_COMMIT();
            CP_WAIT(1);
        } else {
            CP_WAIT(0);
        }
        __syncthreads();

#pragma unroll
        for (int kc = 0; kc < 2; ++kc) {
            uint32_t a[2][4];
            ldsm4(sA[buf] + 2 * ((uint32_t)(m0 * GSTR + kc * 16) + a_lane), a[0]);
            ldsm4(sA[buf] + 2 * ((uint32_t)((m0 + 16) * GSTR + kc * 16) + a_lane), a[1]);
#pragma unroll
            for (int ntp = 0; ntp < 4; ++ntp) {
                uint32_t b[4];
                ldsm4(sB[buf] + 2 * ((uint32_t)((n0 + ntp * 16) * GSTR + kc * 16) + b_lane), b);
                mma_f16(acc[0][2 * ntp],     a[0], b[0], b[1]);
                mma_f16(acc[0][2 * ntp + 1], a[0], b[2], b[3]);
                mma_f16(acc[1][2 * ntp],     a[1], b[0], b[1]);
                mma_f16(acc[1][2 * ntp + 1], a[1], b[2], b[3]);
            }
        }
        __syncthreads();
    }

#pragma unroll
    for (int mt = 0; mt < 2; ++mt) {
        const int rbase = row0 + m0 + mt * 16 + g;
#pragma unroll
        for (int nt = 0; nt < 8; ++nt) {
            const int col = col0 + n0 + nt * 8 + 2 * tg;
            if (HALF_OUT) {
                __half* C = (__half*)Cout;
                *(uint32_t*)(C + (size_t)rbase * D_MODEL + col) =
                    packh2(acc[mt][nt][0] * scale, acc[mt][nt][1] * scale);
                *(uint32_t*)(C + (size_t)(rbase + 8) * D_MODEL + col) =
                    packh2(acc[mt][nt][2] * scale, acc[mt][nt][3] * scale);
            } else {
                float* C = (float*)Cout;
                *(float2*)(C + (size_t)rbase * D_MODEL + col) =
                    make_float2(acc[mt][nt][0], acc[mt][nt][1]);
                *(float2*)(C + (size_t)(rbase + 8) * D_MODEL + col) =
                    make_float2(acc[mt][nt][2], acc[mt][nt][3]);
            }
        }
    }
}

__global__ void __launch_bounds__(256, 2)
qkv_tc_kernel()
{
    const __half* W;
    __half* out;
    float scale;
    if (blockIdx.z == 0)      { W = g_wq; out = g_qh; scale = 0.125f; }
    else if (blockIdx.z == 1) { W = g_wk; out = g_kh; scale = 1.0f; }
    else                      { W = g_wv; out = g_vh; scale = 1.0f; }
    gemm_f16_body<true>(g_xh, W, out, scale);
}

__global__ void __launch_bounds__(256, 2)
oproj_tc_kernel(float* __restrict__ out)
{
    gemm_f16_body<false>(g_ctxh, g_wo, out, 1.0f);
}

// ===========================================================================
// Flash attention, fp16, cp.async double-buffered K/V, register-resident P.
// CTA = (128-query tile, head, batch), 128 threads, 4 warps x 32 q-rows.
// ===========================================================================
#define KST 72   // smem row stride in halves (144B, 16B-aligned rows)

__global__ void __launch_bounds__(128, 2)
attn_f16_kernel()
{
    __shared__ __align__(16) __half Ks[2][64 * KST];
    __shared__ __align__(16) __half Vs[2][64 * KST];

    const int qt = blockIdx.x;
    const int h  = blockIdx.y;
    const int b  = blockIdx.z;
    const int tid  = threadIdx.x;
    const int w    = tid >> 5;
    const int lane = tid & 31;
    const int g  = lane >> 2;
    const int tg = lane & 3;
    const int mi = lane >> 3, ri = lane & 7;
    const int qr = w * 32;

    const uint32_t sK[2] = { smem_u32(Ks[0]), smem_u32(Ks[1]) };
    const uint32_t sV[2] = { smem_u32(Vs[0]), smem_u32(Vs[1]) };
    const uint32_t kb_lane = (uint32_t)(((mi >> 1) * 8 + ri) * KST + (mi & 1) * 8);
    const uint32_t vb_lane = (uint32_t)(((mi & 1) * 8 + ri) * KST + (mi >> 1) * 8);

    const __half* Qg = g_qh + (size_t)(b * SEQ + qt * 128) * D_MODEL + h * DHEAD;
    const __half* Kb = g_kh + (size_t)(b * SEQ) * D_MODEL + h * DHEAD;
    const __half* Vb = g_vh + (size_t)(b * SEQ) * D_MODEL + h * DHEAD;

    auto fillkv = [&](int kt, int buf) {
        const __half* Kg = Kb + (size_t)kt * 64 * D_MODEL;
        const __half* Vg = Vb + (size_t)kt * 64 * D_MODEL;
#pragma unroll
        for (int r = 0; r < 8; ++r) {
            int idx = tid + r * 128;
            int op  = idx >> 9;
            int i   = idx & 511;
            int row = i >> 3;
            int seg = i & 7;
            const __half* src = (op ? Vg : Kg) + (size_t)row * D_MODEL + seg * 8;
            uint32_t dst = (op ? sV[buf] : sK[buf]) + (uint32_t)(row * KST + seg * 8) * 2;
            CP_ASYNC16(dst, src);
        }
    };

    // Preload Q a-frags (already scaled by 0.125 in projection).
    uint32_t qf[2][4][4];
#pragma unroll
    for (int mt = 0; mt < 2; ++mt)
#pragma unroll
        for (int kc = 0; kc < 4; ++kc) {
            const __half* q0 = Qg + (size_t)(qr + mt * 16 + g) * D_MODEL + kc * 16 + 2 * tg;
            const __half* q1 = Qg + (size_t)(qr + mt * 16 + g + 8) * D_MODEL + kc * 16 + 2 * tg;
            qf[mt][kc][0] = *(const uint32_t*)q0;
            qf[mt][kc][1] = *(const uint32_t*)q1;
            qf[mt][kc][2] = *(const uint32_t*)(q0 + 8);
            qf[mt][kc][3] = *(const uint32_t*)(q1 + 8);
        }

    float of[2][8][4];
#pragma unroll
    for (int mt = 0; mt < 2; ++mt)
#pragma unroll
        for (int nt = 0; nt < 8; ++nt)
#pragma unroll
            for (int i = 0; i < 4; ++i) of[mt][nt][i] = 0.0f;
    float mrow[2][2], lrow[2][2];
#pragma unroll
    for (int mt = 0; mt < 2; ++mt) {
        mrow[mt][0] = -3.0e38f; mrow[mt][1] = -3.0e38f;
        lrow[mt][0] = 0.0f;     lrow[mt][1] = 0.0f;
    }

    fillkv(0, 0); CP_COMMIT();

    for (int kt = 0; kt < SEQ / 64; ++kt) {
        const int buf = kt & 1;
        if (kt + 1 < SEQ / 64) {
            fillkv(kt + 1, buf ^ 1); CP_COMMIT();
            CP_WAIT(1);
        } else {
            CP_WAIT(0);
        }
        __syncthreads();

        // ---- S = Qs @ K^T ----
        float sf[2][8][4];
#pragma unroll
        for (int mt = 0; mt < 2; ++mt)
#pragma unroll
            for (int nt = 0; nt < 8; ++nt)
#pragma unroll
                for (int i = 0; i < 4; ++i) sf[mt][nt][i] = 0.0f;

#pragma unroll
        for (int kc = 0; kc < 4; ++kc) {
#pragma unroll
            for (int ntp = 0; ntp < 4; ++ntp) {
                uint32_t bf[4];
                ldsm4(sK[buf] + 2 * ((uint32_t)(ntp * 16 * KST + kc * 16) + kb_lane), bf);
                mma_f16(sf[0][2 * ntp],     qf[0][kc], bf[0], bf[1]);
                mma_f16(sf[0][2 * ntp + 1], qf[0][kc], bf[2], bf[3]);
                mma_f16(sf[1][2 * ntp],     qf[1][kc], bf[0], bf[1]);
                mma_f16(sf[1][2 * ntp + 1], qf[1][kc], bf[2], bf[3]);
            }
        }

        // ---- online softmax ----
        uint32_t pa[2][4][4];
#pragma unroll
        for (int mt = 0; mt < 2; ++mt) {
            float rm0 = -3.0e38f, rm1 = -3.0e38f;
#pragma unroll
            for (int nt = 0; nt < 8; ++nt) {
                rm0 = fmaxf(rm0, fmaxf(sf[mt][nt][0], sf[mt][nt][1]));
                rm1 = fmaxf(rm1, fmaxf(sf[mt][nt][2], sf[mt][nt][3]));
            }
            rm0 = fmaxf(rm0, __shfl_xor_sync(0xffffffffu, rm0, 1));
            rm0 = fmaxf(rm0, __shfl_xor_sync(0xffffffffu, rm0, 2));
            rm1 = fmaxf(rm1, __shfl_xor_sync(0xffffffffu, rm1, 1));
            rm1 = fmaxf(rm1, __shfl_xor_sync(0xffffffffu, rm1, 2));
            const float mn0 = fmaxf(mrow[mt][0], rm0);
            const float mn1 = fmaxf(mrow[mt][1], rm1);
            const float al0 = __expf(mrow[mt][0] - mn0);
            const float al1 = __expf(mrow[mt][1] - mn1);
            float rs0 = 0.0f, rs1 = 0.0f;
#pragma unroll
            for (int nt = 0; nt < 8; ++nt) {
                sf[mt][nt][0] = __expf(sf[mt][nt][0] - mn0); rs0 += sf[mt][nt][0];
                sf[mt][nt][1] = __expf(sf[mt][nt][1] - mn0); rs0 += sf[mt][nt][1];
                sf[mt][nt][2] = __expf(sf[mt][nt][2] - mn1); rs1 += sf[mt][nt][2];
                sf[mt][nt][3] = __expf(sf[mt][nt][3] - mn1); rs1 += sf[mt][nt][3];
            }
            rs0 += __shfl_xor_sync(0xffffffffu, rs0, 1);
            rs0 += __shfl_xor_sync(0xffffffffu, rs0, 2);
            rs1 += __shfl_xor_sync(0xffffffffu, rs1, 1);
            rs1 += __shfl_xor_sync(0xffffffffu, rs1, 2);
            lrow[mt][0] = lrow[mt][0] * al0 + rs0;
            lrow[mt][1] = lrow[mt][1] * al1 + rs1;
#pragma unroll
            for (int nt = 0; nt < 8; ++nt) {
                of[mt][nt][0] *= al0; of[mt][nt][1] *= al0;
                of[mt][nt][2] *= al1; of[mt][nt][3] *= al1;
            }
            mrow[mt][0] = mn0; mrow[mt][1] = mn1;
#pragma unroll
            for (int kc = 0; kc < 4; ++kc) {
                pa[mt][kc][0] = packh2(sf[mt][2 * kc][0],     sf[mt][2 * kc][1]);
                pa[mt][kc][1] = packh2(sf[mt][2 * kc][2],     sf[mt][2 * kc][3]);
                pa[mt][kc][2] = packh2(sf[mt][2 * kc + 1][0], sf[mt][2 * kc + 1][1]);
                pa[mt][kc][3] = packh2(sf[mt][2 * kc + 1][2], sf[mt][2 * kc + 1][3]);
            }
        }

        // ---- O += P @ V ----
#pragma unroll
        for (int kc = 0; kc < 4; ++kc) {
#pragma unroll
            for (int ntp = 0; ntp < 4; ++ntp) {
                uint32_t bf[4];
                ldsm4t(sV[buf] + 2 * ((uint32_t)(kc * 16 * KST + ntp * 16) + vb_lane), bf);
                mma_f16(of[0][2 * ntp],     pa[0][kc], bf[0], bf[1]);
                mma_f16(of[0][2 * ntp + 1], pa[0][kc], bf[2], bf[3]);
                mma_f16(of[1][2 * ntp],     pa[1][kc], bf[0], bf[1]);
                mma_f16(of[1][2 * ntp + 1], pa[1][kc], bf[2], bf[3]);
            }
        }
        __syncthreads();
    }

    // Normalize and write context (fp16).
    __half* Og = g_ctxh + (size_t)(b * SEQ + qt * 128) * D_MODEL + h * DHEAD;
#pragma unroll
    for (int mt = 0; mt < 2; ++mt) {
        const float inv0 = 1.0f / lrow[mt][0];
        const float inv1 = 1.0f / lrow[mt][1];
        const int r0 = qr + mt * 16 + g;
#pragma unroll
        for (int nt = 0; nt < 8; ++nt) {
            const int col = nt * 8 + 2 * tg;
            *(uint32_t*)(Og + (size_t)r0 * D_MODEL + col) =
                packh2(of[mt][nt][0] * inv0, of[mt][nt][1] * inv0);
            *(uint32_t*)(Og + (size_t)(r0 + 8) * D_MODEL + col) =
                packh2(of[mt][nt][2] * inv1, of[mt][nt][3] * inv1);
        }
    }
}

// ---------------------------------------------------------------------------
extern "C" void kernel_launch(void* const* d_in, const int* in_sizes, int n_in,
                              void* d_out, int out_size)
{
    const float* x  = (const float*)d_in[0];
    const float* Wq = (const float*)d_in[1];
    const float* Wk = (const float*)d_in[2];
    const float* Wv = (const float*)d_in[3];
    const float* Wo = (const float*)d_in[4];
    float* out = (float*)d_out;

    cvt_x_kernel<<<1024, 256>>>(x);
    cvt_w_kernel<<<dim3(256, 4), 256>>>(Wq, Wk, Wv, Wo);

    dim3 gqkv(D_MODEL / 128, MTOT / 128, 3);
    qkv_tc_kernel<<<gqkv, 256>>>();

    attn_f16_kernel<<<dim3(SEQ / 128, NHEADS, BATCH), 128>>>();

    dim3 go(D_MODEL / 128, MTOT / 128, 1);
    oproj_tc_kernel<<<go, 256>>>(out);
}

// round 9
// speedup vs baseline: 7.4320x; 1.0199x over previous
#include <cuda_runtime.h>
#include <cuda_fp16.h>
#include <cstdint>

#define D_MODEL 1024
#define NHEADS  16
#define DHEAD   64
#define BATCH   4
#define SEQ     2048
#define MTOT    (BATCH*SEQ)   // 8192

// fp16 scratch (static device globals — allocation-free per harness rules).
__device__ __half g_xh[MTOT*D_MODEL];
__device__ __half g_wq[D_MODEL*D_MODEL];
__device__ __half g_wk[D_MODEL*D_MODEL];
__device__ __half g_wv[D_MODEL*D_MODEL];
__device__ __half g_wo[D_MODEL*D_MODEL];
__device__ __half g_qh[MTOT*D_MODEL];    // pre-scaled by 0.125*log2(e)
__device__ __half g_kh[MTOT*D_MODEL];
__device__ __half g_vh[MTOT*D_MODEL];
__device__ __half g_ctxh[MTOT*D_MODEL];

// ---------------------------------------------------------------------------
// helpers
// ---------------------------------------------------------------------------
__device__ __forceinline__ uint32_t smem_u32(const void* p) {
    uint32_t a;
    asm("{ .reg .u64 t; cvta.to.shared.u64 t, %1; cvt.u32.u64 %0, t; }"
        : "=r"(a) : "l"(p));
    return a;
}
__device__ __forceinline__ uint32_t packh2(float lo, float hi) {
    __half2 h = __floats2half2_rn(lo, hi);
    return *reinterpret_cast<uint32_t*>(&h);
}
__device__ __forceinline__ void ldsm4(uint32_t addr, uint32_t* r) {
    asm volatile("ldmatrix.sync.aligned.m8n8.x4.shared.b16 {%0,%1,%2,%3}, [%4];"
        : "=r"(r[0]), "=r"(r[1]), "=r"(r[2]), "=r"(r[3]) : "r"(addr));
}
__device__ __forceinline__ void ldsm4t(uint32_t addr, uint32_t* r) {
    asm volatile("ldmatrix.sync.aligned.m8n8.x4.trans.shared.b16 {%0,%1,%2,%3}, [%4];"
        : "=r"(r[0]), "=r"(r[1]), "=r"(r[2]), "=r"(r[3]) : "r"(addr));
}
__device__ __forceinline__ void mma_f16(float* d, const uint32_t* a,
                                        uint32_t b0, uint32_t b1) {
    asm volatile(
        "mma.sync.aligned.m16n8k16.row.col.f32.f16.f16.f32 "
        "{%0,%1,%2,%3}, {%4,%5,%6,%7}, {%8,%9}, {%0,%1,%2,%3};"
        : "+f"(d[0]), "+f"(d[1]), "+f"(d[2]), "+f"(d[3])
        : "r"(a[0]), "r"(a[1]), "r"(a[2]), "r"(a[3]), "r"(b0), "r"(b1));
}
#define CP_ASYNC16(dst, src) \
    asm volatile("cp.async.cg.shared.global [%0], [%1], 16;" \
        :: "r"(dst), "l"(src))
#define CP_COMMIT() asm volatile("cp.async.commit_group;" ::: "memory")
#define CP_WAIT(n)  asm volatile("cp.async.wait_group %0;" :: "n"(n) : "memory")

// ---------------------------------------------------------------------------
// fp32 -> fp16 conversion kernels (one-time, ~24MB traffic)
// ---------------------------------------------------------------------------
__global__ void __launch_bounds__(256)
cvt_x_kernel(const float* __restrict__ x)
{
    int base = (blockIdx.x * 256 + threadIdx.x) * 8;
#pragma unroll
    for (int i = 0; i < 8; ++i) {
        int idx = base + i;
        float4 v = *(const float4*)(x + (size_t)idx * 4);
        *(uint2*)(g_xh + (size_t)idx * 4) =
            make_uint2(packh2(v.x, v.y), packh2(v.z, v.w));
    }
}
__global__ void __launch_bounds__(256)
cvt_w_kernel(const float* __restrict__ Wq, const float* __restrict__ Wk,
             const float* __restrict__ Wv, const float* __restrict__ Wo)
{
    const float* src;
    __half* dst;
    switch (blockIdx.y) {
        case 0: src = Wq; dst = g_wq; break;
        case 1: src = Wk; dst = g_wk; break;
        case 2: src = Wv; dst = g_wv; break;
        default: src = Wo; dst = g_wo; break;
    }
    int base = (blockIdx.x * 256 + threadIdx.x) * 4;
#pragma unroll
    for (int i = 0; i < 4; ++i) {
        int idx = base + i;
        float4 v = *(const float4*)(src + (size_t)idx * 4);
        *(uint2*)(dst + (size_t)idx * 4) =
            make_uint2(packh2(v.x, v.y), packh2(v.z, v.w));
    }
}

// ===========================================================================
// GEMM: C[M,N] = A[M,K] @ B[N,K]^T, fp16 in, cp.async double-buffered.
// 128x128 CTA tile, BK=32, 8 warps (4x2), warp tile 32x64.
// ===========================================================================
#define GSTR 40   // smem row stride in halves (80B, 16B-aligned rows)

template<bool HALF_OUT>
__device__ __forceinline__ void gemm_f16_body(
    const __half* __restrict__ A, const __half* __restrict__ B,
    void* __restrict__ Cout, float scale)
{
    __shared__ __align__(16) __half As[2][128 * GSTR];
    __shared__ __align__(16) __half Bs[2][128 * GSTR];

    const int tid = threadIdx.x;
    const int wid = tid >> 5;
    const int lane = tid & 31;
    const int g  = lane >> 2;
    const int tg = lane & 3;
    const int mi = lane >> 3, ri = lane & 7;
    const int m0 = (wid >> 1) * 32;
    const int n0 = (wid & 1) * 64;
    const int row0 = blockIdx.y * 128;
    const int col0 = blockIdx.x * 128;

    const uint32_t sA[2] = { smem_u32(As[0]), smem_u32(As[1]) };
    const uint32_t sB[2] = { smem_u32(Bs[0]), smem_u32(Bs[1]) };
    const uint32_t a_lane = (uint32_t)(((mi & 1) * 8 + ri) * GSTR + (mi >> 1) * 8);
    const uint32_t b_lane = (uint32_t)(((mi >> 1) * 8 + ri) * GSTR + (mi & 1) * 8);

    const __half* Ap = A + (size_t)row0 * D_MODEL;
    const __half* Bp = B + (size_t)col0 * D_MODEL;

    auto fill = [&](int c, int buf) {
#pragma unroll
        for (int r = 0; r < 4; ++r) {
            int idx = tid + r * 256;
            int op  = idx >> 9;
            int i   = idx & 511;
            int row = i >> 2;
            int seg = i & 3;
            const __half* src = (op ? Bp : Ap) + (size_t)row * D_MODEL + c * 32 + seg * 8;
            uint32_t dst = (op ? sB[buf] : sA[buf]) + (uint32_t)(row * GSTR + seg * 8) * 2;
            CP_ASYNC16(dst, src);
        }
    };

    float acc[2][8][4];
#pragma unroll
    for (int mt = 0; mt < 2; ++mt)
#pragma unroll
        for (int nt = 0; nt < 8; ++nt)
#pragma unroll
            for (int i = 0; i < 4; ++i) acc[mt][nt][i] = 0.0f;

    fill(0, 0); CP_COMMIT();

    for (int c = 0; c < D_MODEL / 32; ++c) {
        const int buf = c & 1;
        if (c + 1 < D_MODEL / 32) {
            fill(c + 1, buf ^ 1); CP_COMMIT();
            CP_WAIT(1);
        } else {
            CP_WAIT(0);
        }
        __syncthreads();

#pragma unroll
        for (int kc = 0; kc < 2; ++kc) {
            uint32_t a[2][4];
            ldsm4(sA[buf] + 2 * ((uint32_t)(m0 * GSTR + kc * 16) + a_lane), a[0]);
            ldsm4(sA[buf] + 2 * ((uint32_t)((m0 + 16) * GSTR + kc * 16) + a_lane), a[1]);
#pragma unroll
            for (int ntp = 0; ntp < 4; ++ntp) {
                uint32_t b[4];
                ldsm4(sB[buf] + 2 * ((uint32_t)((n0 + ntp * 16) * GSTR + kc * 16) + b_lane), b);
                mma_f16(acc[0][2 * ntp],     a[0], b[0], b[1]);
                mma_f16(acc[0][2 * ntp + 1], a[0], b[2], b[3]);
                mma_f16(acc[1][2 * ntp],     a[1], b[0], b[1]);
                mma_f16(acc[1][2 * ntp + 1], a[1], b[2], b[3]);
            }
        }
        __syncthreads();
    }

#pragma unroll
    for (int mt = 0; mt < 2; ++mt) {
        const int rbase = row0 + m0 + mt * 16 + g;
#pragma unroll
        for (int nt = 0; nt < 8; ++nt) {
            const int col = col0 + n0 + nt * 8 + 2 * tg;
            if (HALF_OUT) {
                __half* C = (__half*)Cout;
                *(uint32_t*)(C + (size_t)rbase * D_MODEL + col) =
                    packh2(acc[mt][nt][0] * scale, acc[mt][nt][1] * scale);
                *(uint32_t*)(C + (size_t)(rbase + 8) * D_MODEL + col) =
                    packh2(acc[mt][nt][2] * scale, acc[mt][nt][3] * scale);
            } else {
                float* C = (float*)Cout;
                *(float2*)(C + (size_t)rbase * D_MODEL + col) =
                    make_float2(acc[mt][nt][0], acc[mt][nt][1]);
                *(float2*)(C + (size_t)(rbase + 8) * D_MODEL + col) =
                    make_float2(acc[mt][nt][2], acc[mt][nt][3]);
            }
        }
    }
}

__global__ void __launch_bounds__(256, 2)
qkv_tc_kernel()
{
    const __half* W;
    __half* out;
    float scale;
    if (blockIdx.z == 0)      { W = g_wq; out = g_qh; scale = 0.125f * 1.4426950408889634f; }
    else if (blockIdx.z == 1) { W = g_wk; out = g_kh; scale = 1.0f; }
    else                      { W = g_wv; out = g_vh; scale = 1.0f; }
    gemm_f16_body<true>(g_xh, W, out, scale);
}

__global__ void __launch_bounds__(256, 2)
oproj_tc_kernel(float* __restrict__ out)
{
    gemm_f16_body<false>(g_ctxh, g_wo, out, 1.0f);
}

// ===========================================================================
// Flash attention, fp16, cp.async double-buffered K/V, register-resident P.
// CTA = (128-query tile, head, batch), 256 threads, 8 warps x 16 q-rows.
// Softmax in log2 domain (Q pre-scaled by 0.125*log2e); warp-vote rescale skip.
// ===========================================================================
#define KST 72   // smem row stride in halves (144B, 16B-aligned rows)

__global__ void __launch_bounds__(256, 2)
attn_f16_kernel()
{
    __shared__ __align__(16) __half Ks[2][64 * KST];
    __shared__ __align__(16) __half Vs[2][64 * KST];

    const int qt = blockIdx.x;
    const int h  = blockIdx.y;
    const int b  = blockIdx.z;
    const int tid  = threadIdx.x;
    const int w    = tid >> 5;
    const int lane = tid & 31;
    const int g  = lane >> 2;
    const int tg = lane & 3;
    const int mi = lane >> 3, ri = lane & 7;
    const int qr = w * 16;               // warp's 16 query rows within 128-tile

    const uint32_t sK[2] = { smem_u32(Ks[0]), smem_u32(Ks[1]) };
    const uint32_t sV[2] = { smem_u32(Vs[0]), smem_u32(Vs[1]) };
    const uint32_t kb_lane = (uint32_t)(((mi >> 1) * 8 + ri) * KST + (mi & 1) * 8);
    const uint32_t vb_lane = (uint32_t)(((mi & 1) * 8 + ri) * KST + (mi >> 1) * 8);

    const __half* Qg = g_qh + (size_t)(b * SEQ + qt * 128) * D_MODEL + h * DHEAD;
    const __half* Kb = g_kh + (size_t)(b * SEQ) * D_MODEL + h * DHEAD;
    const __half* Vb = g_vh + (size_t)(b * SEQ) * D_MODEL + h * DHEAD;

    auto fillkv = [&](int kt, int buf) {
        const __half* Kg = Kb + (size_t)kt * 64 * D_MODEL;
        const __half* Vg = Vb + (size_t)kt * 64 * D_MODEL;
#pragma unroll
        for (int r = 0; r < 4; ++r) {
            int idx = tid + r * 256;
            int op  = idx >> 9;
            int i   = idx & 511;
            int row = i >> 3;
            int seg = i & 7;
            const __half* src = (op ? Vg : Kg) + (size_t)row * D_MODEL + seg * 8;
            uint32_t dst = (op ? sV[buf] : sK[buf]) + (uint32_t)(row * KST + seg * 8) * 2;
            CP_ASYNC16(dst, src);
        }
    };

    // Preload Q a-frags (already scaled by 0.125*log2e in projection).
    uint32_t qf[4][4];
#pragma unroll
    for (int kc = 0; kc < 4; ++kc) {
        const __half* q0 = Qg + (size_t)(qr + g) * D_MODEL + kc * 16 + 2 * tg;
        const __half* q1 = Qg + (size_t)(qr + g + 8) * D_MODEL + kc * 16 + 2 * tg;
        qf[kc][0] = *(const uint32_t*)q0;
        qf[kc][1] = *(const uint32_t*)q1;
        qf[kc][2] = *(const uint32_t*)(q0 + 8);
        qf[kc][3] = *(const uint32_t*)(q1 + 8);
    }

    float of[8][4];
#pragma unroll
    for (int nt = 0; nt < 8; ++nt)
#pragma unroll
        for (int i = 0; i < 4; ++i) of[nt][i] = 0.0f;
    float m0 = -3.0e38f, m1 = -3.0e38f, l0 = 0.0f, l1 = 0.0f;

    fillkv(0, 0); CP_COMMIT();

    for (int kt = 0; kt < SEQ / 64; ++kt) {
        const int buf = kt & 1;
        if (kt + 1 < SEQ / 64) {
            fillkv(kt + 1, buf ^ 1); CP_COMMIT();
            CP_WAIT(1);
        } else {
            CP_WAIT(0);
        }
        __syncthreads();

        // ---- S = Qs @ K^T (log2 domain) ----
        float sf[8][4];
#pragma unroll
        for (int nt = 0; nt < 8; ++nt)
#pragma unroll
            for (int i = 0; i < 4; ++i) sf[nt][i] = 0.0f;

#pragma unroll
        for (int kc = 0; kc < 4; ++kc) {
#pragma unroll
            for (int ntp = 0; ntp < 4; ++ntp) {
                uint32_t bf[4];
                ldsm4(sK[buf] + 2 * ((uint32_t)(ntp * 16 * KST + kc * 16) + kb_lane), bf);
                mma_f16(sf[2 * ntp],     qf[kc], bf[0], bf[1]);
                mma_f16(sf[2 * ntp + 1], qf[kc], bf[2], bf[3]);
            }
        }

        // ---- online softmax (rows g and g+8) ----
        float rm0 = -3.0e38f, rm1 = -3.0e38f;
#pragma unroll
        for (int nt = 0; nt < 8; ++nt) {
            rm0 = fmaxf(rm0, fmaxf(sf[nt][0], sf[nt][1]));
            rm1 = fmaxf(rm1, fmaxf(sf[nt][2], sf[nt][3]));
        }
        rm0 = fmaxf(rm0, __shfl_xor_sync(0xffffffffu, rm0, 1));
        rm0 = fmaxf(rm0, __shfl_xor_sync(0xffffffffu, rm0, 2));
        rm1 = fmaxf(rm1, __shfl_xor_sync(0xffffffffu, rm1, 1));
        rm1 = fmaxf(rm1, __shfl_xor_sync(0xffffffffu, rm1, 2));
        const bool upd = (rm0 > m0) || (rm1 > m1);
        if (__any_sync(0xffffffffu, upd)) {
            const float mn0 = fmaxf(m0, rm0);
            const float mn1 = fmaxf(m1, rm1);
            const float al0 = exp2f(m0 - mn0);
            const float al1 = exp2f(m1 - mn1);
            l0 *= al0; l1 *= al1;
#pragma unroll
            for (int nt = 0; nt < 8; ++nt) {
                of[nt][0] *= al0; of[nt][1] *= al0;
                of[nt][2] *= al1; of[nt][3] *= al1;
            }
            m0 = mn0; m1 = mn1;
        }
        float rs0 = 0.0f, rs1 = 0.0f;
#pragma unroll
        for (int nt = 0; nt < 8; ++nt) {
            sf[nt][0] = exp2f(sf[nt][0] - m0); rs0 += sf[nt][0];
            sf[nt][1] = exp2f(sf[nt][1] - m0); rs0 += sf[nt][1];
            sf[nt][2] = exp2f(sf[nt][2] - m1); rs1 += sf[nt][2];
            sf[nt][3] = exp2f(sf[nt][3] - m1); rs1 += sf[nt][3];
        }
        rs0 += __shfl_xor_sync(0xffffffffu, rs0, 1);
        rs0 += __shfl_xor_sync(0xffffffffu, rs0, 2);
        rs1 += __shfl_xor_sync(0xffffffffu, rs1, 1);
        rs1 += __shfl_xor_sync(0xffffffffu, rs1, 2);
        l0 += rs0;
        l1 += rs1;

        // P a-frags directly from S C-frags (FA2 layout identity)
        uint32_t pa[4][4];
#pragma unroll
        for (int kc = 0; kc < 4; ++kc) {
            pa[kc][0] = packh2(sf[2 * kc][0],     sf[2 * kc][1]);
            pa[kc][1] = packh2(sf[2 * kc][2],     sf[2 * kc][3]);
            pa[kc][2] = packh2(sf[2 * kc + 1][0], sf[2 * kc + 1][1]);
            pa[kc][3] = packh2(sf[2 * kc + 1][2], sf[2 * kc + 1][3]);
        }

        // ---- O += P @ V ----
#pragma unroll
        for (int kc = 0; kc < 4; ++kc) {
#pragma unroll
            for (int ntp = 0; ntp < 4; ++ntp) {
                uint32_t bf[4];
                ldsm4t(sV[buf] + 2 * ((uint32_t)(kc * 16 * KST + ntp * 16) + vb_lane), bf);
                mma_f16(of[2 * ntp],     pa[kc], bf[0], bf[1]);
                mma_f16(of[2 * ntp + 1], pa[kc], bf[2], bf[3]);
            }
        }
        __syncthreads();
    }

    // Normalize and write context (fp16).
    __half* Og = g_ctxh + (size_t)(b * SEQ + qt * 128) * D_MODEL + h * DHEAD;
    const float inv0 = 1.0f / l0;
    const float inv1 = 1.0f / l1;
    const int r0 = qr + g;
#pragma unroll
    for (int nt = 0; nt < 8; ++nt) {
        const int col = nt * 8 + 2 * tg;
        *(uint32_t*)(Og + (size_t)r0 * D_MODEL + col) =
            packh2(of[nt][0] * inv0, of[nt][1] * inv0);
        *(uint32_t*)(Og + (size_t)(r0 + 8) * D_MODEL + col) =
            packh2(of[nt][2] * inv1, of[nt][3] * inv1);
    }
}

// ---------------------------------------------------------------------------
extern "C" void kernel_launch(void* const* d_in, const int* in_sizes, int n_in,
                              void* d_out, int out_size)
{
    const float* x  = (const float*)d_in[0];
    const float* Wq = (const float*)d_in[1];
    const float* Wk = (const float*)d_in[2];
    const float* Wv = (const float*)d_in[3];
    const float* Wo = (const float*)d_in[4];
    float* out = (float*)d_out;

    cvt_x_kernel<<<1024, 256>>>(x);
    cvt_w_kernel<<<dim3(256, 4), 256>>>(Wq, Wk, Wv, Wo);

    dim3 gqkv(D_MODEL / 128, MTOT / 128, 3);
    qkv_tc_kernel<<<gqkv, 256>>>();

    attn_f16_kernel<<<dim3(SEQ / 128, NHEADS, BATCH), 256>>>();

    dim3 go(D_MODEL / 128, MTOT / 128, 1);
    oproj_tc_kernel<<<go, 256>>>(out);
}

// round 10
// speedup vs baseline: 7.7779x; 1.0465x over previous
#include <cuda_runtime.h>
#include <cuda_fp16.h>
#include <cstdint>

#define D_MODEL 1024
#define NHEADS  16
#define DHEAD   64
#define BATCH   4
#define SEQ     2048
#define MTOT    (BATCH*SEQ)   // 8192

// fp16 scratch (static device globals — allocation-free per harness rules).
__device__ __half g_xh[MTOT*D_MODEL];
__device__ __half g_wq[D_MODEL*D_MODEL];
__device__ __half g_wk[D_MODEL*D_MODEL];
__device__ __half g_wv[D_MODEL*D_MODEL];
__device__ __half g_wo[D_MODEL*D_MODEL];
__device__ __half g_qh[MTOT*D_MODEL];    // pre-scaled by 0.125*log2(e)
__device__ __half g_kh[MTOT*D_MODEL];
__device__ __half g_vh[MTOT*D_MODEL];
__device__ __half g_ctxh[MTOT*D_MODEL];

// ---------------------------------------------------------------------------
// helpers
// ---------------------------------------------------------------------------
__device__ __forceinline__ uint32_t smem_u32(const void* p) {
    uint32_t a;
    asm("{ .reg .u64 t; cvta.to.shared.u64 t, %1; cvt.u32.u64 %0, t; }"
        : "=r"(a) : "l"(p));
    return a;
}
__device__ __forceinline__ uint32_t packh2(float lo, float hi) {
    __half2 h = __floats2half2_rn(lo, hi);
    return *reinterpret_cast<uint32_t*>(&h);
}
__device__ __forceinline__ void ldsm4(uint32_t addr, uint32_t* r) {
    asm volatile("ldmatrix.sync.aligned.m8n8.x4.shared.b16 {%0,%1,%2,%3}, [%4];"
        : "=r"(r[0]), "=r"(r[1]), "=r"(r[2]), "=r"(r[3]) : "r"(addr));
}
__device__ __forceinline__ void ldsm4t(uint32_t addr, uint32_t* r) {
    asm volatile("ldmatrix.sync.aligned.m8n8.x4.trans.shared.b16 {%0,%1,%2,%3}, [%4];"
        : "=r"(r[0]), "=r"(r[1]), "=r"(r[2]), "=r"(r[3]) : "r"(addr));
}
__device__ __forceinline__ void mma_f16(float* d, const uint32_t* a,
                                        uint32_t b0, uint32_t b1) {
    asm volatile(
        "mma.sync.aligned.m16n8k16.row.col.f32.f16.f16.f32 "
        "{%0,%1,%2,%3}, {%4,%5,%6,%7}, {%8,%9}, {%0,%1,%2,%3};"
        : "+f"(d[0]), "+f"(d[1]), "+f"(d[2]), "+f"(d[3])
        : "r"(a[0]), "r"(a[1]), "r"(a[2]), "r"(a[3]), "r"(b0), "r"(b1));
}
#define CP_ASYNC16(dst, src) \
    asm volatile("cp.async.cg.shared.global [%0], [%1], 16;" \
        :: "r"(dst), "l"(src))
#define CP_COMMIT() asm volatile("cp.async.commit_group;" ::: "memory")
#define CP_WAIT(n)  asm volatile("cp.async.wait_group %0;" :: "n"(n) : "memory")

// ---------------------------------------------------------------------------
// fp32 -> fp16 conversion kernels (one-time, ~24MB traffic)
// ---------------------------------------------------------------------------
__global__ void __launch_bounds__(256)
cvt_x_kernel(const float* __restrict__ x)
{
    int base = (blockIdx.x * 256 + threadIdx.x) * 8;
#pragma unroll
    for (int i = 0; i < 8; ++i) {
        int idx = base + i;
        float4 v = *(const float4*)(x + (size_t)idx * 4);
        *(uint2*)(g_xh + (size_t)idx * 4) =
            make_uint2(packh2(v.x, v.y), packh2(v.z, v.w));
    }
}
__global__ void __launch_bounds__(256)
cvt_w_kernel(const float* __restrict__ Wq, const float* __restrict__ Wk,
             const float* __restrict__ Wv, const float* __restrict__ Wo)
{
    const float* src;
    __half* dst;
    switch (blockIdx.y) {
        case 0: src = Wq; dst = g_wq; break;
        case 1: src = Wk; dst = g_wk; break;
        case 2: src = Wv; dst = g_wv; break;
        default: src = Wo; dst = g_wo; break;
    }
    int base = (blockIdx.x * 256 + threadIdx.x) * 4;
#pragma unroll
    for (int i = 0; i < 4; ++i) {
        int idx = base + i;
        float4 v = *(const float4*)(src + (size_t)idx * 4);
        *(uint2*)(dst + (size_t)idx * 4) =
            make_uint2(packh2(v.x, v.y), packh2(v.z, v.w));
    }
}

// ===========================================================================
// GEMM: C[M,N] = A[M,K] @ B[N,K]^T, fp16 in, 3-stage cp.async pipeline,
// single __syncthreads per K-chunk. 128x128 CTA tile, BK=32, 8 warps (4x2).
// ===========================================================================
#define GSTR 40                    // smem row stride in halves (80B)
#define GSTAGE (128 * GSTR)        // halves per operand stage
#define NCH (D_MODEL / 32)         // 32 K-chunks
#define GEMM_DSMEM (6 * GSTAGE * 2)  // 3 stages x (A+B) x 2B = 61440

template<bool HALF_OUT>
__device__ __forceinline__ void gemm_f16_body(
    const __half* __restrict__ A, const __half* __restrict__ B,
    void* __restrict__ Cout, float scale)
{
    extern __shared__ __align__(16) __half dsm[];

    const int tid = threadIdx.x;
    const int wid = tid >> 5;
    const int lane = tid & 31;
    const int g  = lane >> 2;
    const int tg = lane & 3;
    const int mi = lane >> 3, ri = lane & 7;
    const int m0 = (wid >> 1) * 32;
    const int n0 = (wid & 1) * 64;
    const int row0 = blockIdx.y * 128;
    const int col0 = blockIdx.x * 128;

    uint32_t sA[3], sB[3];
#pragma unroll
    for (int s = 0; s < 3; ++s) {
        sA[s] = smem_u32(dsm + s * GSTAGE);
        sB[s] = smem_u32(dsm + (3 + s) * GSTAGE);
    }
    const uint32_t a_lane = (uint32_t)(((mi & 1) * 8 + ri) * GSTR + (mi >> 1) * 8);
    const uint32_t b_lane = (uint32_t)(((mi >> 1) * 8 + ri) * GSTR + (mi & 1) * 8);

    const __half* Ap = A + (size_t)row0 * D_MODEL;
    const __half* Bp = B + (size_t)col0 * D_MODEL;

    auto fill = [&](int c, int s) {
#pragma unroll
        for (int r = 0; r < 4; ++r) {
            int idx = tid + r * 256;
            int op  = idx >> 9;
            int i   = idx & 511;
            int row = i >> 2;
            int seg = i & 3;
            const __half* src = (op ? Bp : Ap) + (size_t)row * D_MODEL + c * 32 + seg * 8;
            uint32_t dst = (op ? sB[s] : sA[s]) + (uint32_t)(row * GSTR + seg * 8) * 2;
            CP_ASYNC16(dst, src);
        }
    };

    float acc[2][8][4];
#pragma unroll
    for (int mt = 0; mt < 2; ++mt)
#pragma unroll
        for (int nt = 0; nt < 8; ++nt)
#pragma unroll
            for (int i = 0; i < 4; ++i) acc[mt][nt][i] = 0.0f;

    fill(0, 0); CP_COMMIT();
    fill(1, 1); CP_COMMIT();

    for (int c = 0; c < NCH; ++c) {
        const int buf = c % 3;
        if (c < NCH - 1) { CP_WAIT(1); } else { CP_WAIT(0); }
        __syncthreads();                       // stage c visible; stage c+2 free
        if (c + 2 < NCH) { fill(c + 2, (c + 2) % 3); CP_COMMIT(); }

#pragma unroll
        for (int kc = 0; kc < 2; ++kc) {
            uint32_t a[2][4];
            ldsm4(sA[buf] + 2 * ((uint32_t)(m0 * GSTR + kc * 16) + a_lane), a[0]);
            ldsm4(sA[buf] + 2 * ((uint32_t)((m0 + 16) * GSTR + kc * 16) + a_lane), a[1]);
#pragma unroll
            for (int ntp = 0; ntp < 4; ++ntp) {
                uint32_t b[4];
                ldsm4(sB[buf] + 2 * ((uint32_t)((n0 + ntp * 16) * GSTR + kc * 16) + b_lane), b);
                mma_f16(acc[0][2 * ntp],     a[0], b[0], b[1]);
                mma_f16(acc[0][2 * ntp + 1], a[0], b[2], b[3]);
                mma_f16(acc[1][2 * ntp],     a[1], b[0], b[1]);
                mma_f16(acc[1][2 * ntp + 1], a[1], b[2], b[3]);
            }
        }
    }

#pragma unroll
    for (int mt = 0; mt < 2; ++mt) {
        const int rbase = row0 + m0 + mt * 16 + g;
#pragma unroll
        for (int nt = 0; nt < 8; ++nt) {
            const int col = col0 + n0 + nt * 8 + 2 * tg;
            if (HALF_OUT) {
                __half* C = (__half*)Cout;
                *(uint32_t*)(C + (size_t)rbase * D_MODEL + col) =
                    packh2(acc[mt][nt][0] * scale, acc[mt][nt][1] * scale);
                *(uint32_t*)(C + (size_t)(rbase + 8) * D_MODEL + col) =
                    packh2(acc[mt][nt][2] * scale, acc[mt][nt][3] * scale);
            } else {
                float* C = (float*)Cout;
                *(float2*)(C + (size_t)rbase * D_MODEL + col) =
                    make_float2(acc[mt][nt][0], acc[mt][nt][1]);
                *(float2*)(C + (size_t)(rbase + 8) * D_MODEL + col) =
                    make_float2(acc[mt][nt][2], acc[mt][nt][3]);
            }
        }
    }
}

__global__ void __launch_bounds__(256, 2)
qkv_tc_kernel()
{
    const __half* W;
    __half* out;
    float scale;
    if (blockIdx.z == 0)      { W = g_wq; out = g_qh; scale = 0.125f * 1.4426950408889634f; }
    else if (blockIdx.z == 1) { W = g_wk; out = g_kh; scale = 1.0f; }
    else                      { W = g_wv; out = g_vh; scale = 1.0f; }
    gemm_f16_body<true>(g_xh, W, out, scale);
}

__global__ void __launch_bounds__(256, 2)
oproj_tc_kernel(float* __restrict__ out)
{
    gemm_f16_body<false>(g_ctxh, g_wo, out, 1.0f);
}

// ===========================================================================
// Flash attention, fp16, 3-stage cp.async K/V pipeline, single sync per tile,
// register-resident P, deferred l-reduction.
// CTA = (128-query tile, head, batch), 256 threads, 8 warps x 16 q-rows.
// ===========================================================================
#define KST 72                     // smem row stride in halves (144B)
#define KSTAGE (64 * KST)          // halves per operand stage
#define NKT (SEQ / 64)             // 32 key tiles
#define ATTN_DSMEM (6 * KSTAGE * 2)  // 3 stages x (K+V) x 2B = 55296

__global__ void __launch_bounds__(256, 2)
attn_f16_kernel()
{
    extern __shared__ __align__(16) __half dsm[];

    const int qt = blockIdx.x;
    const int h  = blockIdx.y;
    const int b  = blockIdx.z;
    const int tid  = threadIdx.x;
    const int w    = tid >> 5;
    const int lane = tid & 31;
    const int g  = lane >> 2;
    const int tg = lane & 3;
    const int mi = lane >> 3, ri = lane & 7;
    const int qr = w * 16;

    uint32_t sK[3], sV[3];
#pragma unroll
    for (int s = 0; s < 3; ++s) {
        sK[s] = smem_u32(dsm + s * KSTAGE);
        sV[s] = smem_u32(dsm + (3 + s) * KSTAGE);
    }
    const uint32_t kb_lane = (uint32_t)(((mi >> 1) * 8 + ri) * KST + (mi & 1) * 8);
    const uint32_t vb_lane = (uint32_t)(((mi & 1) * 8 + ri) * KST + (mi >> 1) * 8);

    const __half* Qg = g_qh + (size_t)(b * SEQ + qt * 128) * D_MODEL + h * DHEAD;
    const __half* Kb = g_kh + (size_t)(b * SEQ) * D_MODEL + h * DHEAD;
    const __half* Vb = g_vh + (size_t)(b * SEQ) * D_MODEL + h * DHEAD;

    auto fillkv = [&](int kt, int s) {
        const __half* Kg = Kb + (size_t)kt * 64 * D_MODEL;
        const __half* Vg = Vb + (size_t)kt * 64 * D_MODEL;
#pragma unroll
        for (int r = 0; r < 4; ++r) {
            int idx = tid + r * 256;
            int op  = idx >> 9;
            int i   = idx & 511;
            int row = i >> 3;
            int seg = i & 7;
            const __half* src = (op ? Vg : Kg) + (size_t)row * D_MODEL + seg * 8;
            uint32_t dst = (op ? sV[s] : sK[s]) + (uint32_t)(row * KST + seg * 8) * 2;
            CP_ASYNC16(dst, src);
        }
    };

    // Preload Q a-frags (already scaled by 0.125*log2e in projection).
    uint32_t qf[4][4];
#pragma unroll
    for (int kc = 0; kc < 4; ++kc) {
        const __half* q0 = Qg + (size_t)(qr + g) * D_MODEL + kc * 16 + 2 * tg;
        const __half* q1 = Qg + (size_t)(qr + g + 8) * D_MODEL + kc * 16 + 2 * tg;
        qf[kc][0] = *(const uint32_t*)q0;
        qf[kc][1] = *(const uint32_t*)q1;
        qf[kc][2] = *(const uint32_t*)(q0 + 8);
        qf[kc][3] = *(const uint32_t*)(q1 + 8);
    }

    float of[8][4];
#pragma unroll
    for (int nt = 0; nt < 8; ++nt)
#pragma unroll
        for (int i = 0; i < 4; ++i) of[nt][i] = 0.0f;
    float m0 = -3.0e38f, m1 = -3.0e38f;
    float l0 = 0.0f, l1 = 0.0f;            // per-thread partials; reduced at end

    fillkv(0, 0); CP_COMMIT();
    fillkv(1, 1); CP_COMMIT();

    for (int kt = 0; kt < NKT; ++kt) {
        const int buf = kt % 3;
        if (kt < NKT - 1) { CP_WAIT(1); } else { CP_WAIT(0); }
        __syncthreads();                   // stage kt visible; stage kt+2 free
        if (kt + 2 < NKT) { fillkv(kt + 2, (kt + 2) % 3); CP_COMMIT(); }

        // ---- S = Qs @ K^T (log2 domain) ----
        float sf[8][4];
#pragma unroll
        for (int nt = 0; nt < 8; ++nt)
#pragma unroll
            for (int i = 0; i < 4; ++i) sf[nt][i] = 0.0f;

#pragma unroll
        for (int kc = 0; kc < 4; ++kc) {
#pragma unroll
            for (int ntp = 0; ntp < 4; ++ntp) {
                uint32_t bf[4];
                ldsm4(sK[buf] + 2 * ((uint32_t)(ntp * 16 * KST + kc * 16) + kb_lane), bf);
                mma_f16(sf[2 * ntp],     qf[kc], bf[0], bf[1]);
                mma_f16(sf[2 * ntp + 1], qf[kc], bf[2], bf[3]);
            }
        }

        // ---- online softmax (rows g and g+8) ----
        float rm0 = -3.0e38f, rm1 = -3.0e38f;
#pragma unroll
        for (int nt = 0; nt < 8; ++nt) {
            rm0 = fmaxf(rm0, fmaxf(sf[nt][0], sf[nt][1]));
            rm1 = fmaxf(rm1, fmaxf(sf[nt][2], sf[nt][3]));
        }
        rm0 = fmaxf(rm0, __shfl_xor_sync(0xffffffffu, rm0, 1));
        rm0 = fmaxf(rm0, __shfl_xor_sync(0xffffffffu, rm0, 2));
        rm1 = fmaxf(rm1, __shfl_xor_sync(0xffffffffu, rm1, 1));
        rm1 = fmaxf(rm1, __shfl_xor_sync(0xffffffffu, rm1, 2));
        const bool upd = (rm0 > m0) || (rm1 > m1);
        if (__any_sync(0xffffffffu, upd)) {
            const float mn0 = fmaxf(m0, rm0);
            const float mn1 = fmaxf(m1, rm1);
            const float al0 = exp2f(m0 - mn0);
            const float al1 = exp2f(m1 - mn1);
            l0 *= al0; l1 *= al1;
#pragma unroll
            for (int nt = 0; nt < 8; ++nt) {
                of[nt][0] *= al0; of[nt][1] *= al0;
                of[nt][2] *= al1; of[nt][3] *= al1;
            }
            m0 = mn0; m1 = mn1;
        }
#pragma unroll
        for (int nt = 0; nt < 8; ++nt) {
            sf[nt][0] = exp2f(sf[nt][0] - m0); l0 += sf[nt][0];
            sf[nt][1] = exp2f(sf[nt][1] - m0); l0 += sf[nt][1];
            sf[nt][2] = exp2f(sf[nt][2] - m1); l1 += sf[nt][2];
            sf[nt][3] = exp2f(sf[nt][3] - m1); l1 += sf[nt][3];
        }

        // P a-frags directly from S C-frags (FA2 layout identity)
        uint32_t pa[4][4];
#pragma unroll
        for (int kc = 0; kc < 4; ++kc) {
            pa[kc][0] = packh2(sf[2 * kc][0],     sf[2 * kc][1]);
            pa[kc][1] = packh2(sf[2 * kc][2],     sf[2 * kc][3]);
            pa[kc][2] = packh2(sf[2 * kc + 1][0], sf[2 * kc + 1][1]);
            pa[kc][3] = packh2(sf[2 * kc + 1][2], sf[2 * kc + 1][3]);
        }

        // ---- O += P @ V ----
#pragma unroll
        for (int kc = 0; kc < 4; ++kc) {
#pragma unroll
            for (int ntp = 0; ntp < 4; ++ntp) {
                uint32_t bf[4];
                ldsm4t(sV[buf] + 2 * ((uint32_t)(kc * 16 * KST + ntp * 16) + vb_lane), bf);
                mma_f16(of[2 * ntp],     pa[kc], bf[0], bf[1]);
                mma_f16(of[2 * ntp + 1], pa[kc], bf[2], bf[3]);
            }
        }
    }

    // Final l reduction across the 4-lane row group, then normalize + store.
    l0 += __shfl_xor_sync(0xffffffffu, l0, 1);
    l0 += __shfl_xor_sync(0xffffffffu, l0, 2);
    l1 += __shfl_xor_sync(0xffffffffu, l1, 1);
    l1 += __shfl_xor_sync(0xffffffffu, l1, 2);

    __half* Og = g_ctxh + (size_t)(b * SEQ + qt * 128) * D_MODEL + h * DHEAD;
    const float inv0 = 1.0f / l0;
    const float inv1 = 1.0f / l1;
    const int r0 = qr + g;
#pragma unroll
    for (int nt = 0; nt < 8; ++nt) {
        const int col = nt * 8 + 2 * tg;
        *(uint32_t*)(Og + (size_t)r0 * D_MODEL + col) =
            packh2(of[nt][0] * inv0, of[nt][1] * inv0);
        *(uint32_t*)(Og + (size_t)(r0 + 8) * D_MODEL + col) =
            packh2(of[nt][2] * inv1, of[nt][3] * inv1);
    }
}

// ---------------------------------------------------------------------------
extern "C" void kernel_launch(void* const* d_in, const int* in_sizes, int n_in,
                              void* d_out, int out_size)
{
    const float* x  = (const float*)d_in[0];
    const float* Wq = (const float*)d_in[1];
    const float* Wk = (const float*)d_in[2];
    const float* Wv = (const float*)d_in[3];
    const float* Wo = (const float*)d_in[4];
    float* out = (float*)d_out;

    cudaFuncSetAttribute(qkv_tc_kernel,
        cudaFuncAttributeMaxDynamicSharedMemorySize, GEMM_DSMEM);
    cudaFuncSetAttribute(oproj_tc_kernel,
        cudaFuncAttributeMaxDynamicSharedMemorySize, GEMM_DSMEM);
    cudaFuncSetAttribute(attn_f16_kernel,
        cudaFuncAttributeMaxDynamicSharedMemorySize, ATTN_DSMEM);

    cvt_x_kernel<<<1024, 256>>>(x);
    cvt_w_kernel<<<dim3(256, 4), 256>>>(Wq, Wk, Wv, Wo);

    dim3 gqkv(D_MODEL / 128, MTOT / 128, 3);
    qkv_tc_kernel<<<gqkv, 256, GEMM_DSMEM>>>();

    attn_f16_kernel<<<dim3(SEQ / 128, NHEADS, BATCH), 256, ATTN_DSMEM>>>();

    dim3 go(D_MODEL / 128, MTOT / 128, 1);
    oproj_tc_kernel<<<go, 256, GEMM_DSMEM>>>(out);
}